// round 3
// baseline (speedup 1.0000x reference)
#include <cuda_runtime.h>

#define TT 120
#define BB 4096
#define FF 48
#define AA 6
#define HH 200
#define NG 800          // 4*H
#define RR 16           // rows per CTA
#define NSTEP 119
#define NTHREADS 800
#define NCTA (BB / RR)  // 256

// ---------------- device scratch (transposed weights + fused biases) ----------------
__device__ float g_Wih1T[FF * NG];          // [k][j], k<48
__device__ float g_Whh1T[HH * NG];          // [k][j], k<200
__device__ float g_Wih2T[(HH + FF) * NG];   // [k][j], k<248 (k<200: h1, k>=200: tiled)
__device__ float g_Whh2T[HH * NG];
__device__ float g_fc1T[(HH + FF) * HH];    // [k][j], j<200
__device__ float g_fc2T[HH * FF];           // [k][j], j<48
__device__ float g_b1[NG];
__device__ float g_b2[NG];

// ---------------- prep: transpose weights, fuse biases ----------------
__global__ void prep_kernel(const float* __restrict__ Wih1, const float* __restrict__ Whh1,
                            const float* __restrict__ bih1, const float* __restrict__ bhh1,
                            const float* __restrict__ Wih2, const float* __restrict__ Whh2,
                            const float* __restrict__ bih2, const float* __restrict__ bhh2,
                            const float* __restrict__ fc1w, const float* __restrict__ fc2w)
{
    int tid = blockIdx.x * blockDim.x + threadIdx.x;
    int stride = gridDim.x * blockDim.x;
    for (int i = tid; i < NG * FF; i += stride) {
        int j = i / FF, k = i % FF;
        g_Wih1T[k * NG + j] = Wih1[i];
    }
    for (int i = tid; i < NG * HH; i += stride) {
        int j = i / HH, k = i % HH;
        g_Whh1T[k * NG + j] = Whh1[i];
        g_Whh2T[k * NG + j] = Whh2[i];
    }
    for (int i = tid; i < NG * (HH + FF); i += stride) {
        int j = i / (HH + FF), k = i % (HH + FF);
        g_Wih2T[k * NG + j] = Wih2[i];
    }
    for (int i = tid; i < HH * (HH + FF); i += stride) {
        int j = i / (HH + FF), k = i % (HH + FF);
        g_fc1T[k * HH + j] = fc1w[i];
    }
    for (int i = tid; i < FF * HH; i += stride) {
        int j = i / HH, k = i % HH;
        g_fc2T[k * FF + j] = fc2w[i];
    }
    for (int i = tid; i < NG; i += stride) {
        g_b1[i] = bih1[i] + bhh1[i];
        g_b2[i] = bih2[i] + bhh2[i];
    }
}

// ---------------- gate accumulation helper ----------------
// acc[r] += sum_k x[r][k] * W_T[k][j]   (KX multiple of 4)
template<int KX>
__device__ __forceinline__ void accum(const float* __restrict__ Wt, const float* __restrict__ xs,
                                      int xstride, float* acc, int j)
{
#pragma unroll 2
    for (int k = 0; k < KX; k += 4) {
        const float* wp = &Wt[k * NG + j];
        float w0 = wp[0];
        float w1 = wp[NG];
        float w2 = wp[2 * NG];
        float w3 = wp[3 * NG];
#pragma unroll
        for (int r = 0; r < RR; r++) {
            const float4 xv = *(const float4*)&xs[r * xstride + k];
            acc[r] += xv.x * w0 + xv.y * w1 + xv.z * w2 + xv.w * w3;
        }
    }
}

__device__ __forceinline__ float sigm(float x) { return 1.0f / (1.0f + expf(-x)); }

// ---------------- main persistent kernel ----------------
__global__ void __launch_bounds__(NTHREADS)
actp_main(const float* __restrict__ tactiles, const float* __restrict__ actions,
          const float* __restrict__ fc1b, const float* __restrict__ fc2b,
          float* __restrict__ out)
{
    extern __shared__ float sm[];
    float* sh1   = sm;                    // RR*200
    float* sh2   = sh1 + RR * HH;         // RR*200
    float* sbuf  = sh2 + RR * HH;         // RR*800  (gates, then fc partials)
    float* sinp  = sbuf + RR * NG;        // RR*48
    float* sout3 = sinp + RR * FF;        // RR*200
    float* sout4 = sout3 + RR * HH;       // RR*48
    float* stil  = sout4 + RR * FF;       // RR*48

    const int tid  = threadIdx.x;
    const int row0 = blockIdx.x * RR;
    const int n_ew = tid % HH;            // elementwise column
    const int rg   = tid / HH;            // row group 0..3 (4 rows each)

    for (int i = tid; i < RR * HH; i += NTHREADS) { sh1[i] = 0.0f; sh2[i] = 0.0f; }
    float c1r[4], c2r[4];
#pragma unroll
    for (int i = 0; i < 4; i++) { c1r[i] = 0.0f; c2r[i] = 0.0f; }
    __syncthreads();

    for (int t = 0; t < NSTEP; t++) {
        // ---- phase 1: inp + tiled ----
        if (tid < RR * FF) {
            int r = tid / FF, f = tid % FF;
            float v;
            if (t > 9) v = sout4[tid];
            else       v = tactiles[((size_t)t * BB + row0 + r) * FF + f];
            sinp[tid] = v;
        }
        if (tid < RR * 12) {
            int r = tid / 12, q = tid % 12;
            float v = (q < 6)
                ? actions[((size_t)(t + 1) * BB + row0 + r) * AA + q]
                : actions[(size_t)(row0 + r) * AA + (q - 6)];
            float* d = &stil[r * FF + q];
            d[0] = v; d[12] = v; d[24] = v; d[36] = v;
        }
        __syncthreads();

        // ---- phase 2: LSTM1 gates ----
        {
            const int j = tid;
            float acc[RR];
            float b = g_b1[j];
#pragma unroll
            for (int r = 0; r < RR; r++) acc[r] = b;
            accum<FF>(g_Wih1T, sinp, FF, acc, j);
            accum<HH>(g_Whh1T, sh1, HH, acc, j);
            bool sg = (j < 2 * HH) || (j >= 3 * HH);
#pragma unroll
            for (int r = 0; r < RR; r++) {
                float v = acc[r];
                sbuf[r * NG + j] = sg ? sigm(v) : tanhf(v);
            }
        }
        __syncthreads();

        // ---- phase 3: LSTM1 cell update ----
#pragma unroll
        for (int i = 0; i < 4; i++) {
            int r = rg * 4 + i;
            float ig = sbuf[r * NG + n_ew];
            float fg = sbuf[r * NG + n_ew + HH];
            float gg = sbuf[r * NG + n_ew + 2 * HH];
            float og = sbuf[r * NG + n_ew + 3 * HH];
            float c = fg * c1r[i] + ig * gg;
            c1r[i] = c;
            sh1[r * HH + n_ew] = og * tanhf(c);
        }
        __syncthreads();

        // ---- phase 4: LSTM2 gates (x2 = [h1, tiled]) ----
        {
            const int j = tid;
            float acc[RR];
            float b = g_b2[j];
#pragma unroll
            for (int r = 0; r < RR; r++) acc[r] = b;
            accum<HH>(g_Wih2T, sh1, HH, acc, j);
            accum<FF>(g_Wih2T + HH * NG, stil, FF, acc, j);
            accum<HH>(g_Whh2T, sh2, HH, acc, j);
            bool sg = (j < 2 * HH) || (j >= 3 * HH);
#pragma unroll
            for (int r = 0; r < RR; r++) {
                float v = acc[r];
                sbuf[r * NG + j] = sg ? sigm(v) : tanhf(v);
            }
        }
        __syncthreads();

        // ---- phase 5: LSTM2 cell update ----
#pragma unroll
        for (int i = 0; i < 4; i++) {
            int r = rg * 4 + i;
            float ig = sbuf[r * NG + n_ew];
            float fg = sbuf[r * NG + n_ew + HH];
            float gg = sbuf[r * NG + n_ew + 2 * HH];
            float og = sbuf[r * NG + n_ew + 3 * HH];
            float c = fg * c2r[i] + ig * gg;
            c2r[i] = c;
            sh2[r * HH + n_ew] = og * tanhf(c);
        }
        __syncthreads();

        // ---- phase 6: fc1 partials (x3 = [h2, inp], K=248) ----
        {
            int j = tid % HH, p = tid / HH;  // p in 0..3, k-chunk of 64
            int k0 = p * 64;
            int k1 = (k0 + 64 < HH + FF) ? (k0 + 64) : (HH + FF);
            float acc[RR];
#pragma unroll
            for (int r = 0; r < RR; r++) acc[r] = 0.0f;
            for (int k = k0; k < k1; k += 4) {
                const float* wp = &g_fc1T[k * HH + j];
                float w0 = wp[0], w1 = wp[HH], w2 = wp[2 * HH], w3 = wp[3 * HH];
                if (k < HH) {
#pragma unroll
                    for (int r = 0; r < RR; r++) {
                        const float4 xv = *(const float4*)&sh2[r * HH + k];
                        acc[r] += xv.x * w0 + xv.y * w1 + xv.z * w2 + xv.w * w3;
                    }
                } else {
#pragma unroll
                    for (int r = 0; r < RR; r++) {
                        const float4 xv = *(const float4*)&sinp[r * FF + (k - HH)];
                        acc[r] += xv.x * w0 + xv.y * w1 + xv.z * w2 + xv.w * w3;
                    }
                }
            }
#pragma unroll
            for (int r = 0; r < RR; r++) sbuf[(p * RR + r) * HH + j] = acc[r];
        }
        __syncthreads();
        // fc1 reduce -> out3
        {
#pragma unroll
            for (int q = 0; q < 4; q++) {
                int idx = tid + q * NTHREADS;     // 0..3199
                int j = idx % HH, r = idx / HH;
                float s = fc1b[j];
#pragma unroll
                for (int p = 0; p < 4; p++) s += sbuf[(p * RR + r) * HH + j];
                sout3[r * HH + j] = tanhf(s);
            }
        }
        __syncthreads();

        // ---- phase 7: fc2 partials ----
        if (tid < 768) {
            int j = tid % FF, p = tid / FF;   // p in 0..15, k-chunk of 13
            int k0 = p * 13;
            int k1 = (k0 + 13 < HH) ? (k0 + 13) : HH;
            float acc[RR];
#pragma unroll
            for (int r = 0; r < RR; r++) acc[r] = 0.0f;
            for (int k = k0; k < k1; k++) {
                float w = g_fc2T[k * FF + j];
#pragma unroll
                for (int r = 0; r < RR; r++) acc[r] += sout3[r * HH + k] * w;
            }
#pragma unroll
            for (int r = 0; r < RR; r++) sbuf[(p * RR + r) * FF + j] = acc[r];
        }
        __syncthreads();
        // fc2 reduce -> out4 (+ global store)
        if (tid < 768) {
            int j = tid % FF, r = tid / FF;
            float s = fc2b[j];
#pragma unroll
            for (int p = 0; p < 16; p++) s += sbuf[(p * RR + r) * FF + j];
            float v = tanhf(s);
            sout4[r * FF + j] = v;
            if (t >= 9) out[((size_t)(t - 9) * BB + row0 + r) * FF + j] = v;
        }
        __syncthreads();
    }
}

// ---------------- launch ----------------
extern "C" void kernel_launch(void* const* d_in, const int* in_sizes, int n_in,
                              void* d_out, int out_size)
{
    (void)in_sizes; (void)n_in; (void)out_size;
    const float* tactiles = (const float*)d_in[0];
    const float* actions  = (const float*)d_in[1];
    const float* W_ih1    = (const float*)d_in[2];
    const float* W_hh1    = (const float*)d_in[3];
    const float* b_ih1    = (const float*)d_in[4];
    const float* b_hh1    = (const float*)d_in[5];
    const float* W_ih2    = (const float*)d_in[6];
    const float* W_hh2    = (const float*)d_in[7];
    const float* b_ih2    = (const float*)d_in[8];
    const float* b_hh2    = (const float*)d_in[9];
    const float* fc1_w    = (const float*)d_in[10];
    const float* fc1_b    = (const float*)d_in[11];
    const float* fc2_w    = (const float*)d_in[12];
    const float* fc2_b    = (const float*)d_in[13];
    float* out = (float*)d_out;

    prep_kernel<<<512, 256>>>(W_ih1, W_hh1, b_ih1, b_hh1,
                              W_ih2, W_hh2, b_ih2, b_hh2,
                              fc1_w, fc2_w);

    size_t smem_bytes = (size_t)(RR * HH * 2 + RR * NG + RR * FF + RR * HH + RR * FF * 2) * sizeof(float);
    cudaFuncSetAttribute(actp_main, cudaFuncAttributeMaxDynamicSharedMemorySize, (int)smem_bytes);

    actp_main<<<NCTA, NTHREADS, smem_bytes>>>(tactiles, actions, fc1_b, fc2_b, out);
}

// round 4
// speedup vs baseline: 1.1499x; 1.1499x over previous
#include <cuda_runtime.h>

#define TT 120
#define BB 4096
#define FF 48
#define AA 6
#define HH 200
#define NG 800          // 4*H
#define RR 16           // rows per CTA
#define PP 8            // row pairs per CTA
#define NSTEP 119
#define NTHREADS 800
#define NCTA (BB / RR)  // 256

typedef unsigned long long u64;

// ---------------- device scratch: quad-packed transposed weights ----------------
// layout: [(k/4) * NJ + j] as float4 holding w[k..k+3] for output j
__device__ float4 g_Wih1Q[12 * NG];         // K=48  -> 12 quads
__device__ float4 g_Whh1Q[50 * NG];         // K=200 -> 50 quads
__device__ float4 g_Wih2Q[62 * NG];         // K=248 -> 62 quads (k<200: h1, k>=200: tiled)
__device__ float4 g_Whh2Q[50 * NG];
__device__ float4 g_fc1Q[62 * HH];          // K=248, 200 outputs
__device__ float  g_fc2T[HH * FF];          // [k][j] scalar transpose
__device__ float  g_b1[NG];
__device__ float  g_b2[NG];

// ---------------- prep: pack weights, fuse biases ----------------
__global__ void prep_kernel(const float* __restrict__ Wih1, const float* __restrict__ Whh1,
                            const float* __restrict__ bih1, const float* __restrict__ bhh1,
                            const float* __restrict__ Wih2, const float* __restrict__ Whh2,
                            const float* __restrict__ bih2, const float* __restrict__ bhh2,
                            const float* __restrict__ fc1w, const float* __restrict__ fc2w)
{
    int tid = blockIdx.x * blockDim.x + threadIdx.x;
    int stride = gridDim.x * blockDim.x;
    float* W1 = (float*)g_Wih1Q;
    for (int i = tid; i < 12 * NG * 4; i += stride) {
        int kk = i & 3, j = (i >> 2) % NG, q = i / (4 * NG);
        W1[i] = Wih1[j * FF + q * 4 + kk];
    }
    float* Wh1 = (float*)g_Whh1Q;
    float* Wh2 = (float*)g_Whh2Q;
    for (int i = tid; i < 50 * NG * 4; i += stride) {
        int kk = i & 3, j = (i >> 2) % NG, q = i / (4 * NG);
        Wh1[i] = Whh1[j * HH + q * 4 + kk];
        Wh2[i] = Whh2[j * HH + q * 4 + kk];
    }
    float* W2 = (float*)g_Wih2Q;
    for (int i = tid; i < 62 * NG * 4; i += stride) {
        int kk = i & 3, j = (i >> 2) % NG, q = i / (4 * NG);
        W2[i] = Wih2[j * (HH + FF) + q * 4 + kk];
    }
    float* F1 = (float*)g_fc1Q;
    for (int i = tid; i < 62 * HH * 4; i += stride) {
        int kk = i & 3, j = (i >> 2) % HH, q = i / (4 * HH);
        F1[i] = fc1w[j * (HH + FF) + q * 4 + kk];
    }
    for (int i = tid; i < FF * HH; i += stride) {
        int j = i / HH, k = i % HH;
        g_fc2T[k * FF + j] = fc2w[i];
    }
    for (int i = tid; i < NG; i += stride) {
        g_b1[i] = bih1[i] + bhh1[i];
        g_b2[i] = bih2[i] + bhh2[i];
    }
}

// ---------------- packed fp32x2 primitives ----------------
__device__ __forceinline__ u64 ffma2(u64 a, u64 b, u64 c) {
    u64 d;
    asm("fma.rn.f32x2 %0, %1, %2, %3;" : "=l"(d) : "l"(a), "l"(b), "l"(c));
    return d;
}
__device__ __forceinline__ u64 pack2(float x, float y) {
    u64 d;
    asm("mov.b64 %0, {%1, %2};" : "=l"(d) : "f"(x), "f"(y));
    return d;
}
__device__ __forceinline__ float2 unpack2(u64 v) {
    float2 r;
    asm("mov.b64 {%0, %1}, %2;" : "=f"(r.x), "=f"(r.y) : "l"(v));
    return r;
}
__device__ __forceinline__ float sigm(float x) { return 1.0f / (1.0f + expf(-x)); }

// acc[p] += sum over NQ quads: pair-x[k] * w[k][j]
// xp: pair-interleaved activations, xs2 = row length in float2 units
template<int NQ>
__device__ __forceinline__ void accumQ(const float4* __restrict__ Wq,
                                       const float* __restrict__ xp,
                                       int xs2, u64* acc, int j)
{
#pragma unroll 2
    for (int q = 0; q < NQ; q++) {
        float4 w = __ldg(&Wq[q * NG + j]);
        u64 w0 = pack2(w.x, w.x), w1 = pack2(w.y, w.y);
        u64 w2 = pack2(w.z, w.z), w3 = pack2(w.w, w.w);
#pragma unroll
        for (int p = 0; p < PP; p++) {
            const float* xb = xp + (p * xs2 + q * 4) * 2;
            ulonglong2 A = *(const ulonglong2*)xb;        // pairs k, k+1
            ulonglong2 B = *(const ulonglong2*)(xb + 4);  // pairs k+2, k+3
            acc[p] = ffma2(A.x, w0, acc[p]);
            acc[p] = ffma2(A.y, w1, acc[p]);
            acc[p] = ffma2(B.x, w2, acc[p]);
            acc[p] = ffma2(B.y, w3, acc[p]);
        }
    }
}

// ---------------- main persistent kernel ----------------
__global__ void __launch_bounds__(NTHREADS)
actp_main(const float* __restrict__ tactiles, const float* __restrict__ actions,
          const float* __restrict__ fc1b, const float* __restrict__ fc2b,
          float* __restrict__ out)
{
    extern __shared__ float sm[];
    // all activation buffers pair-interleaved: elem (p, k) at [(p*K + k)*2 + half]
    float* sh1p = sm;                      // PP*HH*2 = 3200
    float* sh2p = sh1p + PP * HH * 2;      // 3200
    float* sgp  = sh2p + PP * HH * 2;      // PP*NG*2 = 12800 (gates / fc partials)
    float* sinp = sgp + PP * NG * 2;       // PP*FF*2 = 768
    float* so3  = sinp + PP * FF * 2;      // 3200
    float* so4  = so3 + PP * HH * 2;       // 768
    float* stil = so4 + PP * FF * 2;       // 768

    const int tid  = threadIdx.x;
    const int row0 = blockIdx.x * RR;
    const int n_ew = tid % HH;             // elementwise column
    const int rg   = tid / HH;             // row group 0..3 (4 rows each)

    for (int i = tid; i < PP * HH * 2; i += NTHREADS) { sh1p[i] = 0.0f; sh2p[i] = 0.0f; }
    float c1r[4], c2r[4];
#pragma unroll
    for (int i = 0; i < 4; i++) { c1r[i] = 0.0f; c2r[i] = 0.0f; }
    __syncthreads();

    for (int t = 0; t < NSTEP; t++) {
        // ---- phase 1: inp + tiled (pair packed) ----
        if (tid < PP * FF) {               // 384
            int p = tid / FF, f = tid % FF;
            float2 v;
            if (t > 9) {
                v = *(const float2*)&so4[(p * FF + f) * 2];
            } else {
                v.x = tactiles[((size_t)t * BB + row0 + 2 * p) * FF + f];
                v.y = tactiles[((size_t)t * BB + row0 + 2 * p + 1) * FF + f];
            }
            *(float2*)&sinp[(p * FF + f) * 2] = v;
        }
        if (tid < PP * 12) {               // 96
            int p = tid / 12, q = tid % 12;
            float2 v;
            if (q < 6) {
                v.x = actions[((size_t)(t + 1) * BB + row0 + 2 * p) * AA + q];
                v.y = actions[((size_t)(t + 1) * BB + row0 + 2 * p + 1) * AA + q];
            } else {
                v.x = actions[(size_t)(row0 + 2 * p) * AA + (q - 6)];
                v.y = actions[(size_t)(row0 + 2 * p + 1) * AA + (q - 6)];
            }
            float* d = &stil[(p * FF + q) * 2];
            *(float2*)d = v; *(float2*)(d + 24) = v;
            *(float2*)(d + 48) = v; *(float2*)(d + 72) = v;
        }
        __syncthreads();

        // ---- phase 2: LSTM1 gates ----
        {
            const int j = tid;
            float b = g_b1[j];
            u64 bp = pack2(b, b);
            u64 acc[PP];
#pragma unroll
            for (int p = 0; p < PP; p++) acc[p] = bp;
            accumQ<12>(g_Wih1Q, sinp, FF, acc, j);
            accumQ<50>(g_Whh1Q, sh1p, HH, acc, j);
            bool sg = (j < 2 * HH) || (j >= 3 * HH);
#pragma unroll
            for (int p = 0; p < PP; p++) {
                float2 v = unpack2(acc[p]);
                float2 a;
                a.x = sg ? sigm(v.x) : tanhf(v.x);
                a.y = sg ? sigm(v.y) : tanhf(v.y);
                *(float2*)&sgp[(p * NG + j) * 2] = a;
            }
        }
        __syncthreads();

        // ---- phase 3: LSTM1 cell update ----
#pragma unroll
        for (int i = 0; i < 4; i++) {
            int r = rg * 4 + i, p = r >> 1, h = r & 1;
            float ig = sgp[(p * NG + n_ew) * 2 + h];
            float fg = sgp[(p * NG + HH + n_ew) * 2 + h];
            float gg = sgp[(p * NG + 2 * HH + n_ew) * 2 + h];
            float og = sgp[(p * NG + 3 * HH + n_ew) * 2 + h];
            float c = fg * c1r[i] + ig * gg;
            c1r[i] = c;
            sh1p[(p * HH + n_ew) * 2 + h] = og * tanhf(c);
        }
        __syncthreads();

        // ---- phase 4: LSTM2 gates (x2 = [h1, tiled]) ----
        {
            const int j = tid;
            float b = g_b2[j];
            u64 bp = pack2(b, b);
            u64 acc[PP];
#pragma unroll
            for (int p = 0; p < PP; p++) acc[p] = bp;
            accumQ<50>(g_Wih2Q, sh1p, HH, acc, j);
            accumQ<12>(g_Wih2Q + 50 * NG, stil, FF, acc, j);
            accumQ<50>(g_Whh2Q, sh2p, HH, acc, j);
            bool sg = (j < 2 * HH) || (j >= 3 * HH);
#pragma unroll
            for (int p = 0; p < PP; p++) {
                float2 v = unpack2(acc[p]);
                float2 a;
                a.x = sg ? sigm(v.x) : tanhf(v.x);
                a.y = sg ? sigm(v.y) : tanhf(v.y);
                *(float2*)&sgp[(p * NG + j) * 2] = a;
            }
        }
        __syncthreads();

        // ---- phase 5: LSTM2 cell update ----
#pragma unroll
        for (int i = 0; i < 4; i++) {
            int r = rg * 4 + i, p = r >> 1, h = r & 1;
            float ig = sgp[(p * NG + n_ew) * 2 + h];
            float fg = sgp[(p * NG + HH + n_ew) * 2 + h];
            float gg = sgp[(p * NG + 2 * HH + n_ew) * 2 + h];
            float og = sgp[(p * NG + 3 * HH + n_ew) * 2 + h];
            float c = fg * c2r[i] + ig * gg;
            c2r[i] = c;
            sh2p[(p * HH + n_ew) * 2 + h] = og * tanhf(c);
        }
        __syncthreads();

        // ---- phase 6: fc1 partials (x3 = [h2, inp], 62 quads) ----
        {
            int j = tid % HH, pc = tid / HH;      // pc 0..3
            int q0 = pc * 16;
            int q1 = (q0 + 16 < 62) ? (q0 + 16) : 62;
            u64 acc[PP];
#pragma unroll
            for (int p = 0; p < PP; p++) acc[p] = 0ull;
            for (int q = q0; q < q1; q++) {
                float4 w = __ldg(&g_fc1Q[q * HH + j]);
                u64 w0 = pack2(w.x, w.x), w1 = pack2(w.y, w.y);
                u64 w2 = pack2(w.z, w.z), w3 = pack2(w.w, w.w);
                const float* src; int xs2, qq;
                if (q < 50) { src = sh2p; xs2 = HH; qq = q; }
                else        { src = sinp; xs2 = FF; qq = q - 50; }
#pragma unroll
                for (int p = 0; p < PP; p++) {
                    const float* xb = src + (p * xs2 + qq * 4) * 2;
                    ulonglong2 A = *(const ulonglong2*)xb;
                    ulonglong2 B = *(const ulonglong2*)(xb + 4);
                    acc[p] = ffma2(A.x, w0, acc[p]);
                    acc[p] = ffma2(A.y, w1, acc[p]);
                    acc[p] = ffma2(B.x, w2, acc[p]);
                    acc[p] = ffma2(B.y, w3, acc[p]);
                }
            }
#pragma unroll
            for (int p = 0; p < PP; p++) {
                float2 v = unpack2(acc[p]);
                *(float2*)&sgp[((pc * PP + p) * HH + j) * 2] = v;
            }
        }
        __syncthreads();
        // fc1 reduce -> out3
        {
#pragma unroll
            for (int q = 0; q < 2; q++) {
                int idx = tid + q * NTHREADS;     // 0..1599 covers 8p x 200j
                int j = idx % HH, p = idx / HH;
                float bb = fc1b[j];
                float sx = bb, sy = bb;
#pragma unroll
                for (int pc = 0; pc < 4; pc++) {
                    float2 v = *(const float2*)&sgp[((pc * PP + p) * HH + j) * 2];
                    sx += v.x; sy += v.y;
                }
                so3[(p * HH + j) * 2]     = tanhf(sx);
                so3[(p * HH + j) * 2 + 1] = tanhf(sy);
            }
        }
        __syncthreads();

        // ---- phase 7: fc2 partials ----
        if (tid < 768) {
            int j = tid % FF, pc = tid / FF;      // pc 0..15
            int k0 = pc * 13;
            int k1 = (k0 + 13 < HH) ? (k0 + 13) : HH;
            u64 acc[PP];
#pragma unroll
            for (int p = 0; p < PP; p++) acc[p] = 0ull;
            for (int k = k0; k < k1; k++) {
                float w = g_fc2T[k * FF + j];
                u64 wp = pack2(w, w);
#pragma unroll
                for (int p = 0; p < PP; p++) {
                    u64 xv = *(const u64*)&so3[(p * HH + k) * 2];
                    acc[p] = ffma2(xv, wp, acc[p]);
                }
            }
#pragma unroll
            for (int p = 0; p < PP; p++) {
                float2 v = unpack2(acc[p]);
                *(float2*)&sgp[((pc * PP + p) * FF + j) * 2] = v;
            }
        }
        __syncthreads();
        // fc2 reduce -> out4 (+ global store of both rows)
        if (tid < PP * FF) {                      // 384
            int j = tid % FF, p = tid / FF;
            float bb = fc2b[j];
            float sx = bb, sy = bb;
#pragma unroll
            for (int pc = 0; pc < 16; pc++) {
                float2 v = *(const float2*)&sgp[((pc * PP + p) * FF + j) * 2];
                sx += v.x; sy += v.y;
            }
            float v0 = tanhf(sx), v1 = tanhf(sy);
            *(float2*)&so4[(p * FF + j) * 2] = make_float2(v0, v1);
            if (t >= 9) {
                out[((size_t)(t - 9) * BB + row0 + 2 * p) * FF + j]     = v0;
                out[((size_t)(t - 9) * BB + row0 + 2 * p + 1) * FF + j] = v1;
            }
        }
        __syncthreads();
    }
}

// ---------------- launch ----------------
extern "C" void kernel_launch(void* const* d_in, const int* in_sizes, int n_in,
                              void* d_out, int out_size)
{
    (void)in_sizes; (void)n_in; (void)out_size;
    const float* tactiles = (const float*)d_in[0];
    const float* actions  = (const float*)d_in[1];
    const float* W_ih1    = (const float*)d_in[2];
    const float* W_hh1    = (const float*)d_in[3];
    const float* b_ih1    = (const float*)d_in[4];
    const float* b_hh1    = (const float*)d_in[5];
    const float* W_ih2    = (const float*)d_in[6];
    const float* W_hh2    = (const float*)d_in[7];
    const float* b_ih2    = (const float*)d_in[8];
    const float* b_hh2    = (const float*)d_in[9];
    const float* fc1_w    = (const float*)d_in[10];
    const float* fc1_b    = (const float*)d_in[11];
    const float* fc2_w    = (const float*)d_in[12];
    const float* fc2_b    = (const float*)d_in[13];
    float* out = (float*)d_out;

    prep_kernel<<<512, 256>>>(W_ih1, W_hh1, b_ih1, b_hh1,
                              W_ih2, W_hh2, b_ih2, b_hh2,
                              fc1_w, fc2_w);

    size_t smem_bytes = (size_t)(PP * HH * 2 * 2   // sh1p, sh2p
                               + PP * NG * 2       // sgp
                               + PP * FF * 2       // sinp
                               + PP * HH * 2       // so3
                               + PP * FF * 2       // so4
                               + PP * FF * 2)      // stil
                        * sizeof(float);
    cudaFuncSetAttribute(actp_main, cudaFuncAttributeMaxDynamicSharedMemorySize, (int)smem_bytes);

    actp_main<<<NCTA, NTHREADS, smem_bytes>>>(tactiles, actions, fc1_b, fc2_b, out);
}

// round 6
// speedup vs baseline: 1.1551x; 1.0045x over previous
#include <cuda_runtime.h>

#define BB 4096
#define FF 48
#define AA 6
#define HH 200
#define NG 800          // 4*H
#define RR 16           // rows per CTA
#define PP 8            // row pairs per CTA
#define NSTEP 119
#define NTHREADS 800
#define NCTA (BB / RR)  // 256

typedef unsigned long long u64;

// ---------------- device scratch: quad-packed weights ----------------
// gate mats: float4 at [q*800 + col], col = g*200+n, holding W[col][4q..4q+3]
__device__ float4 g_Wih1Q[12 * NG];
__device__ float4 g_Whh1Q[50 * NG];
__device__ float4 g_Wih2Q[62 * NG];
__device__ float4 g_Whh2Q[50 * NG];
__device__ float4 g_fc1Q[62 * HH];   // [q*200 + j]
__device__ float4 g_fc2Q[50 * FF];   // [q*48 + j]
__device__ float  g_b1[NG];
__device__ float  g_b2[NG];

// ---------------- prep ----------------
__device__ __forceinline__ void packW(float* dst, const float* src, int K, int ncol,
                                      int tid, int stride)
{
    int tot = (K / 4) * ncol * 4;
    for (int i = tid; i < tot; i += stride) {
        int kk = i & 3;
        int rest = i >> 2;
        int col = rest % ncol;
        int q = rest / ncol;
        dst[i] = src[col * K + q * 4 + kk];
    }
}

__global__ void prep_kernel(const float* __restrict__ Wih1, const float* __restrict__ Whh1,
                            const float* __restrict__ bih1, const float* __restrict__ bhh1,
                            const float* __restrict__ Wih2, const float* __restrict__ Whh2,
                            const float* __restrict__ bih2, const float* __restrict__ bhh2,
                            const float* __restrict__ fc1w, const float* __restrict__ fc2w)
{
    int tid = blockIdx.x * blockDim.x + threadIdx.x;
    int stride = gridDim.x * blockDim.x;
    packW((float*)g_Wih1Q, Wih1, FF, NG, tid, stride);
    packW((float*)g_Whh1Q, Whh1, HH, NG, tid, stride);
    packW((float*)g_Wih2Q, Wih2, HH + FF, NG, tid, stride);
    packW((float*)g_Whh2Q, Whh2, HH, NG, tid, stride);
    packW((float*)g_fc1Q, fc1w, HH + FF, HH, tid, stride);
    packW((float*)g_fc2Q, fc2w, HH, FF, tid, stride);
    for (int i = tid; i < NG; i += stride) {
        g_b1[i] = bih1[i] + bhh1[i];
        g_b2[i] = bih2[i] + bhh2[i];
    }
}

// ---------------- packed fp32x2 primitives ----------------
__device__ __forceinline__ u64 ffma2(u64 a, u64 b, u64 c) {
    u64 d;
    asm("fma.rn.f32x2 %0, %1, %2, %3;" : "=l"(d) : "l"(a), "l"(b), "l"(c));
    return d;
}
__device__ __forceinline__ u64 pack2(float x, float y) {
    u64 d;
    asm("mov.b64 %0, {%1, %2};" : "=l"(d) : "f"(x), "f"(y));
    return d;
}
__device__ __forceinline__ float2 unpack2(u64 v) {
    float2 r;
    asm("mov.b64 {%0, %1}, %2;" : "=f"(r.x), "=f"(r.y) : "l"(v));
    return r;
}
__device__ __forceinline__ float sigm(float x) { return 1.0f / (1.0f + expf(-x)); }

// gate accumulation: 4 gate columns (n, n+200, n+400, n+600), 2 row-pairs
template<int NQ, int K>
__device__ __forceinline__ void accumG(const float4* __restrict__ Wq,
                                       const float* __restrict__ x,
                                       int p0, int n, u64 acc[4][2])
{
#pragma unroll 1
    for (int q = 0; q < NQ; q++) {
        float4 w0 = __ldg(&Wq[q * NG + n]);
        float4 w1 = __ldg(&Wq[q * NG + n + HH]);
        float4 w2 = __ldg(&Wq[q * NG + n + 2 * HH]);
        float4 w3 = __ldg(&Wq[q * NG + n + 3 * HH]);
#pragma unroll
        for (int pi = 0; pi < 2; pi++) {
            const float* xb = x + ((p0 + pi) * K + q * 4) * 2;
            ulonglong2 A = *(const ulonglong2*)xb;        // pairs k, k+1
            ulonglong2 B = *(const ulonglong2*)(xb + 4);  // pairs k+2, k+3
            acc[0][pi] = ffma2(A.x, pack2(w0.x, w0.x), acc[0][pi]);
            acc[0][pi] = ffma2(A.y, pack2(w0.y, w0.y), acc[0][pi]);
            acc[0][pi] = ffma2(B.x, pack2(w0.z, w0.z), acc[0][pi]);
            acc[0][pi] = ffma2(B.y, pack2(w0.w, w0.w), acc[0][pi]);
            acc[1][pi] = ffma2(A.x, pack2(w1.x, w1.x), acc[1][pi]);
            acc[1][pi] = ffma2(A.y, pack2(w1.y, w1.y), acc[1][pi]);
            acc[1][pi] = ffma2(B.x, pack2(w1.z, w1.z), acc[1][pi]);
            acc[1][pi] = ffma2(B.y, pack2(w1.w, w1.w), acc[1][pi]);
            acc[2][pi] = ffma2(A.x, pack2(w2.x, w2.x), acc[2][pi]);
            acc[2][pi] = ffma2(A.y, pack2(w2.y, w2.y), acc[2][pi]);
            acc[2][pi] = ffma2(B.x, pack2(w2.z, w2.z), acc[2][pi]);
            acc[2][pi] = ffma2(B.y, pack2(w2.w, w2.w), acc[2][pi]);
            acc[3][pi] = ffma2(A.x, pack2(w3.x, w3.x), acc[3][pi]);
            acc[3][pi] = ffma2(A.y, pack2(w3.y, w3.y), acc[3][pi]);
            acc[3][pi] = ffma2(B.x, pack2(w3.z, w3.z), acc[3][pi]);
            acc[3][pi] = ffma2(B.y, pack2(w3.w, w3.w), acc[3][pi]);
        }
    }
}

// ---------------- main persistent kernel ----------------
__global__ void __launch_bounds__(NTHREADS)
actp_main(const float* __restrict__ tactiles, const float* __restrict__ actions,
          const float* __restrict__ fc1b, const float* __restrict__ fc2b,
          float* __restrict__ out)
{
    extern __shared__ float sm[];
    // pair-interleaved: elem (p, k) at [(p*K + k)*2 + half]
    float* sh1b = sm;                        // 2 buffers x PP*HH*2 = 6400
    float* sh2b = sh1b + 2 * PP * HH * 2;    // 6400
    float* sinp = sh2b + 2 * PP * HH * 2;    // 768
    float* stil = sinp + PP * FF * 2;        // 768
    float* so3  = stil + PP * FF * 2;        // 3200
    float* so4  = so3 + PP * HH * 2;         // 768

    const int tid  = threadIdx.x;
    const int row0 = blockIdx.x * RR;
    const int n    = tid % HH;               // unit / fc1 column
    const int pg   = tid / HH;               // pair group 0..3
    const int p0   = 2 * pg;

    for (int i = tid; i < 2 * PP * HH * 2; i += NTHREADS) { sh1b[i] = 0.0f; sh2b[i] = 0.0f; }

    // per-thread persistent state: biases + cell states (2 pairs each)
    float b1g[4], b2g[4];
#pragma unroll
    for (int g = 0; g < 4; g++) { b1g[g] = g_b1[g * HH + n]; b2g[g] = g_b2[g * HH + n]; }
    const float bf1 = fc1b[n];
    const float bf2 = (tid < 384) ? fc2b[tid % FF] : 0.0f;
    float2 c1s[2], c2s[2];
#pragma unroll
    for (int i = 0; i < 2; i++) { c1s[i] = make_float2(0.f, 0.f); c2s[i] = make_float2(0.f, 0.f); }
    __syncthreads();

    for (int t = 0; t < NSTEP; t++) {
        const int cur = t & 1, nxt = cur ^ 1;
        float* sh1c = sh1b + cur * PP * HH * 2;
        float* sh1n = sh1b + nxt * PP * HH * 2;
        float* sh2c = sh2b + cur * PP * HH * 2;
        float* sh2n = sh2b + nxt * PP * HH * 2;

        // ---- phase 1: inp + tiled ----
        if (tid < PP * FF) {
            int p = tid / FF, f = tid % FF;
            float2 v;
            if (t > 9) {
                v = *(const float2*)&so4[(p * FF + f) * 2];
            } else {
                v.x = tactiles[((size_t)t * BB + row0 + 2 * p) * FF + f];
                v.y = tactiles[((size_t)t * BB + row0 + 2 * p + 1) * FF + f];
            }
            *(float2*)&sinp[(p * FF + f) * 2] = v;
        }
        if (tid < PP * 12) {
            int p = tid / 12, q = tid % 12;
            float2 v;
            if (q < 6) {
                v.x = actions[((size_t)(t + 1) * BB + row0 + 2 * p) * AA + q];
                v.y = actions[((size_t)(t + 1) * BB + row0 + 2 * p + 1) * AA + q];
            } else {
                v.x = actions[(size_t)(row0 + 2 * p) * AA + (q - 6)];
                v.y = actions[(size_t)(row0 + 2 * p + 1) * AA + (q - 6)];
            }
            float* d = &stil[(p * FF + q) * 2];
            *(float2*)d = v; *(float2*)(d + 24) = v;
            *(float2*)(d + 48) = v; *(float2*)(d + 72) = v;
        }
        __syncthreads();

        // ---- LSTM1: gates + cell update fused ----
        {
            u64 acc[4][2];
#pragma unroll
            for (int g = 0; g < 4; g++) {
                u64 b = pack2(b1g[g], b1g[g]);
                acc[g][0] = b; acc[g][1] = b;
            }
            accumG<12, FF>(g_Wih1Q, sinp, p0, n, acc);
            accumG<50, HH>(g_Whh1Q, sh1c, p0, n, acc);
#pragma unroll
            for (int pi = 0; pi < 2; pi++) {
                float2 iv = unpack2(acc[0][pi]);
                float2 fv = unpack2(acc[1][pi]);
                float2 gv = unpack2(acc[2][pi]);
                float2 ov = unpack2(acc[3][pi]);
                float cx = sigm(fv.x) * c1s[pi].x + sigm(iv.x) * tanhf(gv.x);
                float cy = sigm(fv.y) * c1s[pi].y + sigm(iv.y) * tanhf(gv.y);
                c1s[pi] = make_float2(cx, cy);
                float hx = sigm(ov.x) * tanhf(cx);
                float hy = sigm(ov.y) * tanhf(cy);
                *(float2*)&sh1n[((p0 + pi) * HH + n) * 2] = make_float2(hx, hy);
            }
        }
        __syncthreads();

        // ---- LSTM2: gates + cell update fused (x2 = [h1_new, tiled], recur h2_old) ----
        {
            u64 acc[4][2];
#pragma unroll
            for (int g = 0; g < 4; g++) {
                u64 b = pack2(b2g[g], b2g[g]);
                acc[g][0] = b; acc[g][1] = b;
            }
            accumG<50, HH>(g_Wih2Q, sh1n, p0, n, acc);
            accumG<12, FF>(g_Wih2Q + 50 * NG, stil, p0, n, acc);
            accumG<50, HH>(g_Whh2Q, sh2c, p0, n, acc);
#pragma unroll
            for (int pi = 0; pi < 2; pi++) {
                float2 iv = unpack2(acc[0][pi]);
                float2 fv = unpack2(acc[1][pi]);
                float2 gv = unpack2(acc[2][pi]);
                float2 ov = unpack2(acc[3][pi]);
                float cx = sigm(fv.x) * c2s[pi].x + sigm(iv.x) * tanhf(gv.x);
                float cy = sigm(fv.y) * c2s[pi].y + sigm(iv.y) * tanhf(gv.y);
                c2s[pi] = make_float2(cx, cy);
                float hx = sigm(ov.x) * tanhf(cx);
                float hy = sigm(ov.y) * tanhf(cy);
                *(float2*)&sh2n[((p0 + pi) * HH + n) * 2] = make_float2(hx, hy);
            }
        }
        __syncthreads();

        // ---- fc1: out3 = tanh([h2_new, inp] @ fc1_w.T + b), full K per thread ----
        {
            u64 acc[2] = {0ull, 0ull};
#pragma unroll 1
            for (int q = 0; q < 62; q++) {
                float4 w = __ldg(&g_fc1Q[q * HH + n]);
                const float* src; int xs, qq;
                if (q < 50) { src = sh2n; xs = HH; qq = q; }
                else        { src = sinp; xs = FF; qq = q - 50; }
#pragma unroll
                for (int pi = 0; pi < 2; pi++) {
                    const float* xb = src + ((p0 + pi) * xs + qq * 4) * 2;
                    ulonglong2 A = *(const ulonglong2*)xb;
                    ulonglong2 B = *(const ulonglong2*)(xb + 4);
                    acc[pi] = ffma2(A.x, pack2(w.x, w.x), acc[pi]);
                    acc[pi] = ffma2(A.y, pack2(w.y, w.y), acc[pi]);
                    acc[pi] = ffma2(B.x, pack2(w.z, w.z), acc[pi]);
                    acc[pi] = ffma2(B.y, pack2(w.w, w.w), acc[pi]);
                }
            }
#pragma unroll
            for (int pi = 0; pi < 2; pi++) {
                float2 v = unpack2(acc[pi]);
                *(float2*)&so3[((p0 + pi) * HH + n) * 2] =
                    make_float2(tanhf(v.x + bf1), tanhf(v.y + bf1));
            }
        }
        __syncthreads();

        // ---- fc2: out4 = tanh(out3 @ fc2_w.T + b) ----
        if (tid < 384) {
            int j = tid % FF, p = tid / FF;    // 48 cols x 8 pairs
            u64 acc = 0ull;
#pragma unroll 1
            for (int q = 0; q < 50; q++) {
                float4 w = __ldg(&g_fc2Q[q * FF + j]);
                const float* xb = so3 + (p * HH + q * 4) * 2;
                ulonglong2 A = *(const ulonglong2*)xb;
                ulonglong2 B = *(const ulonglong2*)(xb + 4);
                acc = ffma2(A.x, pack2(w.x, w.x), acc);
                acc = ffma2(A.y, pack2(w.y, w.y), acc);
                acc = ffma2(B.x, pack2(w.z, w.z), acc);
                acc = ffma2(B.y, pack2(w.w, w.w), acc);
            }
            float2 v = unpack2(acc);
            float v0 = tanhf(v.x + bf2), v1 = tanhf(v.y + bf2);
            *(float2*)&so4[(p * FF + j) * 2] = make_float2(v0, v1);
            if (t >= 9) {
                out[((size_t)(t - 9) * BB + row0 + 2 * p) * FF + j]     = v0;
                out[((size_t)(t - 9) * BB + row0 + 2 * p + 1) * FF + j] = v1;
            }
        }
        __syncthreads();
    }
}

// ---------------- launch ----------------
extern "C" void kernel_launch(void* const* d_in, const int* in_sizes, int n_in,
                              void* d_out, int out_size)
{
    (void)in_sizes; (void)n_in; (void)out_size;
    const float* tactiles = (const float*)d_in[0];
    const float* actions  = (const float*)d_in[1];
    const float* W_ih1    = (const float*)d_in[2];
    const float* W_hh1    = (const float*)d_in[3];
    const float* b_ih1    = (const float*)d_in[4];
    const float* b_hh1    = (const float*)d_in[5];
    const float* W_ih2    = (const float*)d_in[6];
    const float* W_hh2    = (const float*)d_in[7];
    const float* b_ih2    = (const float*)d_in[8];
    const float* b_hh2    = (const float*)d_in[9];
    const float* fc1_w    = (const float*)d_in[10];
    const float* fc1_b    = (const float*)d_in[11];
    const float* fc2_w    = (const float*)d_in[12];
    const float* fc2_b    = (const float*)d_in[13];
    float* out = (float*)d_out;

    prep_kernel<<<512, 256>>>(W_ih1, W_hh1, b_ih1, b_hh1,
                              W_ih2, W_hh2, b_ih2, b_hh2,
                              fc1_w, fc2_w);

    size_t smem_bytes = (size_t)(2 * PP * HH * 2 * 2   // sh1b, sh2b (double-buffered)
                               + PP * FF * 2           // sinp
                               + PP * FF * 2           // stil
                               + PP * HH * 2           // so3
                               + PP * FF * 2)          // so4
                        * sizeof(float);
    cudaFuncSetAttribute(actp_main, cudaFuncAttributeMaxDynamicSharedMemorySize, (int)smem_bytes);

    actp_main<<<NCTA, NTHREADS, smem_bytes>>>(tactiles, actions, fc1_b, fc2_b, out);
}

// round 10
// speedup vs baseline: 1.4822x; 1.2832x over previous
#include <cuda_runtime.h>

#define BB 4096
#define FF 48
#define AA 6
#define HH 200
#define NG 800          // 4*H
#define RR 16           // rows per CTA
#define PP 8            // row pairs per CTA
#define NSTEP 119
#define NTHREADS 400
#define NCTA (BB / RR)  // 256
#define SHB (PP * HH * 2)   // 3200 floats per h buffer

typedef unsigned long long u64;

// ---------------- device scratch: quad-packed weights ----------------
// gate mats: float4 at [q*800 + col], col = g*200+n, holding W[col][4q..4q+3]
__device__ float4 g_Wih1Q[12 * NG];
__device__ float4 g_Whh1Q[50 * NG];
__device__ float4 g_Wih2Q[62 * NG];   // only q<50 (h1 part) used by gates
__device__ float4 g_Wtil2Q[3 * NG];   // folded tiled part: 12 k values
__device__ float4 g_Whh2Q[50 * NG];
__device__ float4 g_fc1Q[62 * HH];    // [q*200 + j]
__device__ float4 g_fc2Q[50 * FF];    // [q*48 + j]
__device__ float  g_b1[NG];
__device__ float  g_b2[NG];

// ---------------- prep ----------------
__device__ __forceinline__ void packW(float* dst, const float* src, int K, int ncol,
                                      int tid, int stride)
{
    int tot = (K / 4) * ncol * 4;
    for (int i = tid; i < tot; i += stride) {
        int kk = i & 3;
        int rest = i >> 2;
        int col = rest % ncol;
        int q = rest / ncol;
        dst[i] = src[col * K + q * 4 + kk];
    }
}

__global__ void prep_kernel(const float* __restrict__ Wih1, const float* __restrict__ Whh1,
                            const float* __restrict__ bih1, const float* __restrict__ bhh1,
                            const float* __restrict__ Wih2, const float* __restrict__ Whh2,
                            const float* __restrict__ bih2, const float* __restrict__ bhh2,
                            const float* __restrict__ fc1w, const float* __restrict__ fc2w)
{
    int tid = blockIdx.x * blockDim.x + threadIdx.x;
    int stride = gridDim.x * blockDim.x;
    packW((float*)g_Wih1Q, Wih1, FF, NG, tid, stride);
    packW((float*)g_Whh1Q, Whh1, HH, NG, tid, stride);
    packW((float*)g_Wih2Q, Wih2, HH + FF, NG, tid, stride);
    packW((float*)g_Whh2Q, Whh2, HH, NG, tid, stride);
    packW((float*)g_fc1Q, fc1w, HH + FF, HH, tid, stride);
    packW((float*)g_fc2Q, fc2w, HH, FF, tid, stride);
    // folded tiled weights: sum of 4 tile replicas, 12 k values -> 3 quads
    float* Wt = (float*)g_Wtil2Q;
    for (int i = tid; i < 3 * NG * 4; i += stride) {
        int kk = i & 3;
        int rest = i >> 2;
        int col = rest % NG;
        int q = rest / NG;
        int k = q * 4 + kk;
        float s = 0.0f;
#pragma unroll
        for (int r = 0; r < 4; r++) s += Wih2[col * (HH + FF) + HH + k + 12 * r];
        Wt[i] = s;
    }
    for (int i = tid; i < NG; i += stride) {
        g_b1[i] = bih1[i] + bhh1[i];
        g_b2[i] = bih2[i] + bhh2[i];
    }
}

// ---------------- packed fp32x2 primitives ----------------
__device__ __forceinline__ u64 ffma2(u64 a, u64 b, u64 c) {
    u64 d;
    asm("fma.rn.f32x2 %0, %1, %2, %3;" : "=l"(d) : "l"(a), "l"(b), "l"(c));
    return d;
}
__device__ __forceinline__ u64 pack2(float x, float y) {
    u64 d;
    asm("mov.b64 %0, {%1, %2};" : "=l"(d) : "f"(x), "f"(y));
    return d;
}
__device__ __forceinline__ float2 unpack2(u64 v) {
    float2 r;
    asm("mov.b64 {%0, %1}, %2;" : "=f"(r.x), "=f"(r.y) : "l"(v));
    return r;
}
__device__ __forceinline__ float sigm(float x) { return 1.0f / (1.0f + expf(-x)); }

// gate accumulation: 4 gate columns x 4 row-pairs per thread.
// xb already offset to this thread's first pair (p0*K*2).
template<int NQ, int K>
__device__ __forceinline__ void accumG4(const float4* __restrict__ Wq, int n,
                                        const float* __restrict__ xb, u64 acc[4][4])
{
#pragma unroll 1
    for (int q = 0; q < NQ; q++) {
        float4 w0 = __ldg(&Wq[q * NG + n]);
        float4 w1 = __ldg(&Wq[q * NG + n + HH]);
        float4 w2 = __ldg(&Wq[q * NG + n + 2 * HH]);
        float4 w3 = __ldg(&Wq[q * NG + n + 3 * HH]);
#pragma unroll
        for (int pi = 0; pi < 4; pi++) {
            const float* xp = xb + (pi * K + q * 4) * 2;
            ulonglong2 A = *(const ulonglong2*)xp;
            ulonglong2 B = *(const ulonglong2*)(xp + 4);
            acc[0][pi] = ffma2(A.x, pack2(w0.x, w0.x), acc[0][pi]);
            acc[0][pi] = ffma2(A.y, pack2(w0.y, w0.y), acc[0][pi]);
            acc[0][pi] = ffma2(B.x, pack2(w0.z, w0.z), acc[0][pi]);
            acc[0][pi] = ffma2(B.y, pack2(w0.w, w0.w), acc[0][pi]);
            acc[1][pi] = ffma2(A.x, pack2(w1.x, w1.x), acc[1][pi]);
            acc[1][pi] = ffma2(A.y, pack2(w1.y, w1.y), acc[1][pi]);
            acc[1][pi] = ffma2(B.x, pack2(w1.z, w1.z), acc[1][pi]);
            acc[1][pi] = ffma2(B.y, pack2(w1.w, w1.w), acc[1][pi]);
            acc[2][pi] = ffma2(A.x, pack2(w2.x, w2.x), acc[2][pi]);
            acc[2][pi] = ffma2(A.y, pack2(w2.y, w2.y), acc[2][pi]);
            acc[2][pi] = ffma2(B.x, pack2(w2.z, w2.z), acc[2][pi]);
            acc[2][pi] = ffma2(B.y, pack2(w2.w, w2.w), acc[2][pi]);
            acc[3][pi] = ffma2(A.x, pack2(w3.x, w3.x), acc[3][pi]);
            acc[3][pi] = ffma2(A.y, pack2(w3.y, w3.y), acc[3][pi]);
            acc[3][pi] = ffma2(B.x, pack2(w3.z, w3.z), acc[3][pi]);
            acc[3][pi] = ffma2(B.y, pack2(w3.w, w3.w), acc[3][pi]);
        }
    }
}

// ---------------- main persistent kernel ----------------
__global__ void __launch_bounds__(NTHREADS, 2)
actp_main(const float* __restrict__ tactiles, const float* __restrict__ actions,
          const float* __restrict__ fc1b, const float* __restrict__ fc2b,
          float* __restrict__ out)
{
    extern __shared__ float sm[];
    // pair-interleaved: elem (p, k) at [(p*K + k)*2 + half]
    float* sh1b = sm;                    // 2 x SHB
    float* sh2b = sh1b + 2 * SHB;        // 2 x SHB
    float* sinp = sh2b + 2 * SHB;        // PP*FF*2 = 768
    float* stil = sinp + PP * FF * 2;    // PP*12*2 = 192 (unreplicated tiled base)
    float* so3  = stil + PP * 12 * 2;    // 3200

    const int tid  = threadIdx.x;
    const int row0 = blockIdx.x * RR;
    const int n    = tid % HH;           // unit / fc1 column
    const int pg   = tid / HH;           // pair-group 0..1 (4 pairs each)
    const int p0   = 4 * pg;

    for (int i = tid; i < 2 * SHB; i += NTHREADS) { sh1b[i] = 0.0f; sh2b[i] = 0.0f; }

    float2 c1s[4], c2s[4];
#pragma unroll
    for (int i = 0; i < 4; i++) { c1s[i] = make_float2(0.f, 0.f); c2s[i] = make_float2(0.f, 0.f); }

    // prologue staging: sinp <- tactiles[0]; stil <- [actions[1], state=actions[0]]
    if (tid < PP * FF) {
        int p = tid / FF, f = tid % FF;
        float2 v;
        v.x = tactiles[((size_t)0 * BB + row0 + 2 * p) * FF + f];
        v.y = tactiles[((size_t)0 * BB + row0 + 2 * p + 1) * FF + f];
        *(float2*)&sinp[(p * FF + f) * 2] = v;
    }
    if (tid < PP * 12) {
        int p = tid / 12, q = tid % 12;
        float2 v;
        if (q < 6) {
            v.x = actions[((size_t)1 * BB + row0 + 2 * p) * AA + q];
            v.y = actions[((size_t)1 * BB + row0 + 2 * p + 1) * AA + q];
        } else {
            v.x = actions[(size_t)(row0 + 2 * p) * AA + (q - 6)];
            v.y = actions[(size_t)(row0 + 2 * p + 1) * AA + (q - 6)];
        }
        *(float2*)&stil[(p * 12 + q) * 2] = v;
    }
    __syncthreads();

    for (int t = 0; t < NSTEP; t++) {
        const int cur = t & 1, nxt = cur ^ 1;
        float* sh1c = sh1b + cur * SHB;
        float* sh1n = sh1b + nxt * SHB;
        float* sh2c = sh2b + cur * SHB;
        float* sh2n = sh2b + nxt * SHB;

        // ---- LSTM1: gates + cell update fused ----
        {
            u64 acc[4][4];
#pragma unroll
            for (int g = 0; g < 4; g++) {
                float b = g_b1[g * HH + n];
                u64 bp = pack2(b, b);
#pragma unroll
                for (int pi = 0; pi < 4; pi++) acc[g][pi] = bp;
            }
            accumG4<12, FF>(g_Wih1Q, n, sinp + p0 * FF * 2, acc);
            accumG4<50, HH>(g_Whh1Q, n, sh1c + p0 * HH * 2, acc);
#pragma unroll
            for (int pi = 0; pi < 4; pi++) {
                float2 iv = unpack2(acc[0][pi]);
                float2 fv = unpack2(acc[1][pi]);
                float2 gv = unpack2(acc[2][pi]);
                float2 ov = unpack2(acc[3][pi]);
                float cx = sigm(fv.x) * c1s[pi].x + sigm(iv.x) * tanhf(gv.x);
                float cy = sigm(fv.y) * c1s[pi].y + sigm(iv.y) * tanhf(gv.y);
                c1s[pi] = make_float2(cx, cy);
                float hx = sigm(ov.x) * tanhf(cx);
                float hy = sigm(ov.y) * tanhf(cy);
                *(float2*)&sh1n[((p0 + pi) * HH + n) * 2] = make_float2(hx, hy);
            }
        }
        __syncthreads();

        // ---- LSTM2: gates + cell update fused ----
        {
            u64 acc[4][4];
#pragma unroll
            for (int g = 0; g < 4; g++) {
                float b = g_b2[g * HH + n];
                u64 bp = pack2(b, b);
#pragma unroll
                for (int pi = 0; pi < 4; pi++) acc[g][pi] = bp;
            }
            accumG4<50, HH>(g_Wih2Q, n, sh1n + p0 * HH * 2, acc);
            accumG4<3, 12>(g_Wtil2Q, n, stil + p0 * 12 * 2, acc);
            accumG4<50, HH>(g_Whh2Q, n, sh2c + p0 * HH * 2, acc);
#pragma unroll
            for (int pi = 0; pi < 4; pi++) {
                float2 iv = unpack2(acc[0][pi]);
                float2 fv = unpack2(acc[1][pi]);
                float2 gv = unpack2(acc[2][pi]);
                float2 ov = unpack2(acc[3][pi]);
                float cx = sigm(fv.x) * c2s[pi].x + sigm(iv.x) * tanhf(gv.x);
                float cy = sigm(fv.y) * c2s[pi].y + sigm(iv.y) * tanhf(gv.y);
                c2s[pi] = make_float2(cx, cy);
                float hx = sigm(ov.x) * tanhf(cx);
                float hy = sigm(ov.y) * tanhf(cy);
                *(float2*)&sh2n[((p0 + pi) * HH + n) * 2] = make_float2(hx, hy);
            }
        }
        __syncthreads();

        // ---- fc1: out3 = tanh([h2_new, inp] @ fc1_w.T + b), 4 pairs per thread ----
        {
            u64 acc4[4] = {0ull, 0ull, 0ull, 0ull};
            const float* xh = sh2n + p0 * HH * 2;
#pragma unroll 1
            for (int q = 0; q < 50; q++) {
                float4 w = __ldg(&g_fc1Q[q * HH + n]);
#pragma unroll
                for (int pi = 0; pi < 4; pi++) {
                    const float* xp = xh + (pi * HH + q * 4) * 2;
                    ulonglong2 A = *(const ulonglong2*)xp;
                    ulonglong2 B = *(const ulonglong2*)(xp + 4);
                    acc4[pi] = ffma2(A.x, pack2(w.x, w.x), acc4[pi]);
                    acc4[pi] = ffma2(A.y, pack2(w.y, w.y), acc4[pi]);
                    acc4[pi] = ffma2(B.x, pack2(w.z, w.z), acc4[pi]);
                    acc4[pi] = ffma2(B.y, pack2(w.w, w.w), acc4[pi]);
                }
            }
            const float* xi = sinp + p0 * FF * 2;
#pragma unroll 1
            for (int q = 0; q < 12; q++) {
                float4 w = __ldg(&g_fc1Q[(q + 50) * HH + n]);
#pragma unroll
                for (int pi = 0; pi < 4; pi++) {
                    const float* xp = xi + (pi * FF + q * 4) * 2;
                    ulonglong2 A = *(const ulonglong2*)xp;
                    ulonglong2 B = *(const ulonglong2*)(xp + 4);
                    acc4[pi] = ffma2(A.x, pack2(w.x, w.x), acc4[pi]);
                    acc4[pi] = ffma2(A.y, pack2(w.y, w.y), acc4[pi]);
                    acc4[pi] = ffma2(B.x, pack2(w.z, w.z), acc4[pi]);
                    acc4[pi] = ffma2(B.y, pack2(w.w, w.w), acc4[pi]);
                }
            }
            float bf1v = fc1b[n];
#pragma unroll
            for (int pi = 0; pi < 4; pi++) {
                float2 v = unpack2(acc4[pi]);
                *(float2*)&so3[((p0 + pi) * HH + n) * 2] =
                    make_float2(tanhf(v.x + bf1v), tanhf(v.y + bf1v));
            }
        }
        __syncthreads();

        // ---- fc2 + next-step staging ----
        if (tid < PP * FF) {                     // 384 threads: j x p
            int j = tid % FF, p = tid / FF;
            u64 acc = 0ull;
            const float* xb = so3 + p * HH * 2;
#pragma unroll 1
            for (int q = 0; q < 50; q++) {
                float4 w = __ldg(&g_fc2Q[q * FF + j]);
                const float* xp = xb + q * 8;
                ulonglong2 A = *(const ulonglong2*)xp;
                ulonglong2 B = *(const ulonglong2*)(xp + 4);
                acc = ffma2(A.x, pack2(w.x, w.x), acc);
                acc = ffma2(A.y, pack2(w.y, w.y), acc);
                acc = ffma2(B.x, pack2(w.z, w.z), acc);
                acc = ffma2(B.y, pack2(w.w, w.w), acc);
            }
            float2 v = unpack2(acc);
            float bb = fc2b[j];
            float v0 = tanhf(v.x + bb), v1 = tanhf(v.y + bb);
            if (t >= 9) {
                out[((size_t)(t - 9) * BB + row0 + 2 * p) * FF + j]     = v0;
                out[((size_t)(t - 9) * BB + row0 + 2 * p + 1) * FF + j] = v1;
            }
            // stage sinp for step t+1
            float2 nv;
            if (t + 1 <= 9) {
                nv.x = tactiles[((size_t)(t + 1) * BB + row0 + 2 * p) * FF + j];
                nv.y = tactiles[((size_t)(t + 1) * BB + row0 + 2 * p + 1) * FF + j];
            } else {
                nv = make_float2(v0, v1);
            }
            *(float2*)&sinp[(p * FF + j) * 2] = nv;
        }
        // stage action part of stil for step t+1 (state part is persistent)
        if (tid < PP * 6 && t + 1 < NSTEP) {
            int p = tid / 6, q = tid % 6;
            float2 v;
            v.x = actions[((size_t)(t + 2) * BB + row0 + 2 * p) * AA + q];
            v.y = actions[((size_t)(t + 2) * BB + row0 + 2 * p + 1) * AA + q];
            *(float2*)&stil[(p * 12 + q) * 2] = v;
        }
        __syncthreads();
    }
}

// ---------------- launch ----------------
extern "C" void kernel_launch(void* const* d_in, const int* in_sizes, int n_in,
                              void* d_out, int out_size)
{
    (void)in_sizes; (void)n_in; (void)out_size;
    const float* tactiles = (const float*)d_in[0];
    const float* actions  = (const float*)d_in[1];
    const float* W_ih1    = (const float*)d_in[2];
    const float* W_hh1    = (const float*)d_in[3];
    const float* b_ih1    = (const float*)d_in[4];
    const float* b_hh1    = (const float*)d_in[5];
    const float* W_ih2    = (const float*)d_in[6];
    const float* W_hh2    = (const float*)d_in[7];
    const float* b_ih2    = (const float*)d_in[8];
    const float* b_hh2    = (const float*)d_in[9];
    const float* fc1_w    = (const float*)d_in[10];
    const float* fc1_b    = (const float*)d_in[11];
    const float* fc2_w    = (const float*)d_in[12];
    const float* fc2_b    = (const float*)d_in[13];
    float* out = (float*)d_out;

    prep_kernel<<<512, 256>>>(W_ih1, W_hh1, b_ih1, b_hh1,
                              W_ih2, W_hh2, b_ih2, b_hh2,
                              fc1_w, fc2_w);

    size_t smem_bytes = (size_t)(4 * SHB          // sh1b, sh2b double-buffered
                               + PP * FF * 2      // sinp
                               + PP * 12 * 2      // stil
                               + SHB)             // so3
                        * sizeof(float);
    cudaFuncSetAttribute(actp_main, cudaFuncAttributeMaxDynamicSharedMemorySize, (int)smem_bytes);

    actp_main<<<NCTA, NTHREADS, smem_bytes>>>(tactiles, actions, fc1_b, fc2_b, out);
}

// round 11
// speedup vs baseline: 3.8153x; 2.5740x over previous
#include <cuda_runtime.h>
#include <cuda_bf16.h>
#include <cstring>

#define BB 4096
#define FF 48
#define AA 6
#define HH 200
#define NG 800
#define RRW 16              // rows per CTA
#define NSTEP 119
#define NTHREADS 320
#define NCTA (BB / RRW)     // 256

#define ASTR 744            // arena row stride (bf16 elems)
#define GSTR 808            // gates row stride (fp32)

// arena column bases
#define C_INP  0
#define C_H1   56
#define C_TIL  256
#define C_H2   272
#define C_INP2 472
#define C_O3   528

// GEMM shapes
#define KS1 16   // gemm1: A cols 0..255
#define KS2 26   // gemm2: A cols 56..471
#define KS3 16   // fc1:   A cols 272..527
#define KS4 13   // fc2:   A cols 528..735
#define NT1 100
#define NT3 25
#define NT4 6

typedef unsigned int u32;
typedef unsigned long long u64;

// ---------------- packed weight fragments: uint4 = {bh0,bh1,bl0,bl1} ----------------
__device__ uint4 g_B1[NT1 * KS1 * 32];
__device__ uint4 g_B2[NT1 * KS2 * 32];
__device__ uint4 g_B3[NT3 * KS3 * 32];
__device__ uint4 g_B4[NT4 * KS4 * 32];
__device__ float g_b1[NG];
__device__ float g_b2[NG];

// ---------------- prep ----------------
__device__ __forceinline__ unsigned short bfbits(float v) {
    __nv_bfloat16 b = __float2bfloat16(v);
    unsigned short u; memcpy(&u, &b, 2); return u;
}
__device__ __forceinline__ uint4 packFrag(const float w[4]) {
    unsigned short h[4], l[4];
#pragma unroll
    for (int e = 0; e < 4; e++) {
        __nv_bfloat16 hb = __float2bfloat16(w[e]);
        h[e] = bfbits(w[e]);
        l[e] = bfbits(w[e] - __bfloat162float(hb));
    }
    uint4 r;
    r.x = (u32)h[0] | ((u32)h[1] << 16);
    r.y = (u32)h[2] | ((u32)h[3] << 16);
    r.z = (u32)l[0] | ((u32)l[1] << 16);
    r.w = (u32)l[2] | ((u32)l[3] << 16);
    return r;
}

__global__ void prep_kernel(const float* __restrict__ Wih1, const float* __restrict__ Whh1,
                            const float* __restrict__ bih1, const float* __restrict__ bhh1,
                            const float* __restrict__ Wih2, const float* __restrict__ Whh2,
                            const float* __restrict__ bih2, const float* __restrict__ bhh2,
                            const float* __restrict__ fc1w, const float* __restrict__ fc2w)
{
    int tid = blockIdx.x * blockDim.x + threadIdx.x;
    int stride = gridDim.x * blockDim.x;
    for (int i = tid; i < NG; i += stride) {
        g_b1[i] = bih1[i] + bhh1[i];
        g_b2[i] = bih2[i] + bhh2[i];
    }
    // GEMM1: K-span [inp48 | zp8 | h1 200] = 256
    for (int i = tid; i < NT1 * KS1 * 32; i += stride) {
        int lane = i & 31, ks = (i >> 5) % KS1, nt = i / (32 * KS1);
        int n = nt * 8 + (lane >> 2);
        int k0 = ks * 16 + (lane & 3) * 2;
        float w[4];
#pragma unroll
        for (int e = 0; e < 4; e++) {
            int k = k0 + (e >> 1) * 8 + (e & 1);
            float v;
            if (k < 48)       v = Wih1[n * 48 + k];
            else if (k < 56)  v = 0.0f;
            else              v = Whh1[n * 200 + (k - 56)];
            w[e] = v;
        }
        g_B1[i] = packFrag(w);
    }
    // GEMM2: K-span [h1 200 | til_folded 12 | zp4 | h2 200] = 416
    for (int i = tid; i < NT1 * KS2 * 32; i += stride) {
        int lane = i & 31, ks = (i >> 5) % KS2, nt = i / (32 * KS2);
        int n = nt * 8 + (lane >> 2);
        int k0 = ks * 16 + (lane & 3) * 2;
        float w[4];
#pragma unroll
        for (int e = 0; e < 4; e++) {
            int k = k0 + (e >> 1) * 8 + (e & 1);
            float v;
            if (k < 200) v = Wih2[n * 248 + k];
            else if (k < 212) {
                v = 0.0f;
#pragma unroll
                for (int r = 0; r < 4; r++) v += Wih2[n * 248 + 200 + (k - 200) + 12 * r];
            }
            else if (k < 216) v = 0.0f;
            else              v = Whh2[n * 200 + (k - 216)];
            w[e] = v;
        }
        g_B2[i] = packFrag(w);
    }
    // fc1: K-span [h2 200 | inp 48 | zp8] = 256, N = 200
    for (int i = tid; i < NT3 * KS3 * 32; i += stride) {
        int lane = i & 31, ks = (i >> 5) % KS3, nt = i / (32 * KS3);
        int n = nt * 8 + (lane >> 2);
        int k0 = ks * 16 + (lane & 3) * 2;
        float w[4];
#pragma unroll
        for (int e = 0; e < 4; e++) {
            int k = k0 + (e >> 1) * 8 + (e & 1);
            w[e] = (k < 248) ? fc1w[n * 248 + k] : 0.0f;
        }
        g_B3[i] = packFrag(w);
    }
    // fc2: K-span [o3 200 | zp8] = 208, N = 48
    for (int i = tid; i < NT4 * KS4 * 32; i += stride) {
        int lane = i & 31, ks = (i >> 5) % KS4, nt = i / (32 * KS4);
        int n = nt * 8 + (lane >> 2);
        int k0 = ks * 16 + (lane & 3) * 2;
        float w[4];
#pragma unroll
        for (int e = 0; e < 4; e++) {
            int k = k0 + (e >> 1) * 8 + (e & 1);
            w[e] = (k < 200) ? fc2w[n * 200 + k] : 0.0f;
        }
        g_B4[i] = packFrag(w);
    }
}

// ---------------- mma primitives ----------------
__device__ __forceinline__ u32 smem_u32(const void* p) {
    return (u32)__cvta_generic_to_shared(p);
}
__device__ __forceinline__ void ldm_x4(u32 a[4], u32 addr) {
    asm volatile("ldmatrix.sync.aligned.m8n8.x4.shared.b16 {%0,%1,%2,%3}, [%4];"
                 : "=r"(a[0]), "=r"(a[1]), "=r"(a[2]), "=r"(a[3]) : "r"(addr));
}
__device__ __forceinline__ void mma_bf16(float c[4], const u32 a[4], u32 b0, u32 b1) {
    asm volatile("mma.sync.aligned.m16n8k16.row.col.f32.bf16.bf16.f32 "
                 "{%0,%1,%2,%3}, {%4,%5,%6,%7}, {%8,%9}, {%0,%1,%2,%3};"
                 : "+f"(c[0]), "+f"(c[1]), "+f"(c[2]), "+f"(c[3])
                 : "r"(a[0]), "r"(a[1]), "r"(a[2]), "r"(a[3]), "r"(b0), "r"(b1));
}
__device__ __forceinline__ float sigm(float x) { return 1.0f / (1.0f + expf(-x)); }

__device__ __forceinline__ void splitStore(float v, __nv_bfloat16* hiA, __nv_bfloat16* loA, int idx) {
    __nv_bfloat16 h = __float2bfloat16(v);
    hiA[idx] = h;
    loA[idx] = __float2bfloat16(v - __bfloat162float(h));
}

// ---------------- main persistent kernel ----------------
__global__ void __launch_bounds__(NTHREADS, 2)
actp_main(const float* __restrict__ tactiles, const float* __restrict__ actions,
          const float* __restrict__ fc1b, const float* __restrict__ fc2b,
          float* __restrict__ out)
{
    extern __shared__ char smemraw[];
    __nv_bfloat16* aHi = (__nv_bfloat16*)smemraw;
    __nv_bfloat16* aLo = aHi + RRW * ASTR;
    float* gates = (float*)(smemraw + 2 * RRW * ASTR * 2);

    const int tid  = threadIdx.x;
    const int lane = tid & 31;
    const int warp = tid >> 5;
    const int row0 = blockIdx.x * RRW;

    // zero arena (incl. all pads)
    {
        u32* z = (u32*)smemraw;
        int nz = (2 * RRW * ASTR * 2) / 4;
        for (int i = tid; i < nz; i += NTHREADS) z[i] = 0;
    }
    __syncthreads();

    // prologue staging
    for (int idx = tid; idx < RRW * FF; idx += NTHREADS) {
        int r = idx / FF, c = idx % FF;
        float v = tactiles[((size_t)0 * BB + row0 + r) * FF + c];
        splitStore(v, aHi, aLo, r * ASTR + C_INP + c);
        splitStore(v, aHi, aLo, r * ASTR + C_INP2 + c);
    }
    for (int idx = tid; idx < RRW * 12; idx += NTHREADS) {
        int r = idx / 12, c = idx % 12;
        float v = (c < 6)
            ? actions[((size_t)1 * BB + row0 + r) * AA + c]
            : actions[(size_t)(row0 + r) * AA + (c - 6)];
        splitStore(v, aHi, aLo, r * ASTR + C_TIL + c);
    }
    float c1s[10], c2s[10];
#pragma unroll
    for (int i = 0; i < 10; i++) { c1s[i] = 0.0f; c2s[i] = 0.0f; }
    __syncthreads();

    // ldmatrix lane geometry
    const int mq   = lane >> 3;
    const int ldr  = (mq & 1) * 8 + (lane & 7);
    const int ldc  = (mq >> 1) * 8;
    const u32 aHiB = smem_u32(aHi) + (u32)(ldr * ASTR + ldc) * 2;
    const u32 aLoB = smem_u32(aLo) + (u32)(ldr * ASTR + ldc) * 2;
    const int crow = lane >> 2;           // C fragment row
    const int ccol = (lane & 3) * 2;      // C fragment col base

    for (int t = 0; t < NSTEP; t++) {
        // ===== Phase A: GEMM1 -> gates =====
        {
            float C[10][4];
#pragma unroll
            for (int j = 0; j < 10; j++)
#pragma unroll
                for (int e = 0; e < 4; e++) C[j][e] = 0.0f;
            const int ntb = warp * 10;
#pragma unroll 1
            for (int ks = 0; ks < KS1; ks++) {
                u32 Ah[4], Al[4];
                ldm_x4(Ah, aHiB + (u32)(C_INP * 2 + ks * 32));
                ldm_x4(Al, aLoB + (u32)(C_INP * 2 + ks * 32));
#pragma unroll
                for (int j = 0; j < 10; j++) {
                    uint4 b = __ldg(&g_B1[((ntb + j) * KS1 + ks) * 32 + lane]);
                    mma_bf16(C[j], Ah, b.x, b.y);
                    mma_bf16(C[j], Ah, b.z, b.w);
                    mma_bf16(C[j], Al, b.x, b.y);
                }
            }
#pragma unroll
            for (int j = 0; j < 10; j++) {
                int col = (ntb + j) * 8 + ccol;
                *(float2*)&gates[crow * GSTR + col]       = make_float2(C[j][0], C[j][1]);
                *(float2*)&gates[(crow + 8) * GSTR + col] = make_float2(C[j][2], C[j][3]);
            }
        }
        __syncthreads();

        // ===== Phase B: LSTM1 cell update -> h1 (arena, in place) =====
#pragma unroll
        for (int i = 0; i < 10; i++) {
            int idx = tid + NTHREADS * i;
            int r = idx / HH, u = idx % HH;
            float gi = gates[r * GSTR + u]        + __ldg(&g_b1[u]);
            float gf = gates[r * GSTR + u + 200]  + __ldg(&g_b1[u + 200]);
            float gg = gates[r * GSTR + u + 400]  + __ldg(&g_b1[u + 400]);
            float go = gates[r * GSTR + u + 600]  + __ldg(&g_b1[u + 600]);
            float c = sigm(gf) * c1s[i] + sigm(gi) * tanhf(gg);
            c1s[i] = c;
            splitStore(sigm(go) * tanhf(c), aHi, aLo, r * ASTR + C_H1 + u);
        }
        __syncthreads();

        // ===== Phase C: GEMM2 -> gates =====
        {
            float C[10][4];
#pragma unroll
            for (int j = 0; j < 10; j++)
#pragma unroll
                for (int e = 0; e < 4; e++) C[j][e] = 0.0f;
            const int ntb = warp * 10;
#pragma unroll 1
            for (int ks = 0; ks < KS2; ks++) {
                u32 Ah[4], Al[4];
                ldm_x4(Ah, aHiB + (u32)(C_H1 * 2 + ks * 32));
                ldm_x4(Al, aLoB + (u32)(C_H1 * 2 + ks * 32));
#pragma unroll
                for (int j = 0; j < 10; j++) {
                    uint4 b = __ldg(&g_B2[((ntb + j) * KS2 + ks) * 32 + lane]);
                    mma_bf16(C[j], Ah, b.x, b.y);
                    mma_bf16(C[j], Ah, b.z, b.w);
                    mma_bf16(C[j], Al, b.x, b.y);
                }
            }
#pragma unroll
            for (int j = 0; j < 10; j++) {
                int col = (ntb + j) * 8 + ccol;
                *(float2*)&gates[crow * GSTR + col]       = make_float2(C[j][0], C[j][1]);
                *(float2*)&gates[(crow + 8) * GSTR + col] = make_float2(C[j][2], C[j][3]);
            }
        }
        __syncthreads();

        // ===== Phase D: LSTM2 cell update -> h2 =====
#pragma unroll
        for (int i = 0; i < 10; i++) {
            int idx = tid + NTHREADS * i;
            int r = idx / HH, u = idx % HH;
            float gi = gates[r * GSTR + u]        + __ldg(&g_b2[u]);
            float gf = gates[r * GSTR + u + 200]  + __ldg(&g_b2[u + 200]);
            float gg = gates[r * GSTR + u + 400]  + __ldg(&g_b2[u + 400]);
            float go = gates[r * GSTR + u + 600]  + __ldg(&g_b2[u + 600]);
            float c = sigm(gf) * c2s[i] + sigm(gi) * tanhf(gg);
            c2s[i] = c;
            splitStore(sigm(go) * tanhf(c), aHi, aLo, r * ASTR + C_H2 + u);
        }
        __syncthreads();

        // ===== Phase E: fc1 GEMM -> gates[0..199] (preacts) =====
        {
            float C[3][4];
#pragma unroll
            for (int j = 0; j < 3; j++)
#pragma unroll
                for (int e = 0; e < 4; e++) C[j][e] = 0.0f;
            const int cnt = (warp < 5) ? 3 : 2;
#pragma unroll 1
            for (int ks = 0; ks < KS3; ks++) {
                u32 Ah[4], Al[4];
                ldm_x4(Ah, aHiB + (u32)(C_H2 * 2 + ks * 32));
                ldm_x4(Al, aLoB + (u32)(C_H2 * 2 + ks * 32));
#pragma unroll
                for (int j = 0; j < 3; j++) {
                    if (j < cnt) {
                        int nt = warp + 10 * j;
                        uint4 b = __ldg(&g_B3[(nt * KS3 + ks) * 32 + lane]);
                        mma_bf16(C[j], Ah, b.x, b.y);
                        mma_bf16(C[j], Ah, b.z, b.w);
                        mma_bf16(C[j], Al, b.x, b.y);
                    }
                }
            }
#pragma unroll
            for (int j = 0; j < 3; j++) {
                if (j < cnt) {
                    int col = (warp + 10 * j) * 8 + ccol;
                    *(float2*)&gates[crow * GSTR + col]       = make_float2(C[j][0], C[j][1]);
                    *(float2*)&gates[(crow + 8) * GSTR + col] = make_float2(C[j][2], C[j][3]);
                }
            }
        }
        __syncthreads();

        // ===== Phase F: o3 = tanh(preact + fc1b) -> arena =====
#pragma unroll
        for (int i = 0; i < 10; i++) {
            int idx = tid + NTHREADS * i;
            int r = idx / HH, u = idx % HH;
            float v = tanhf(gates[r * GSTR + u] + __ldg(&fc1b[u]));
            splitStore(v, aHi, aLo, r * ASTR + C_O3 + u);
        }
        __syncthreads();

        // ===== Phase G: fc2 GEMM + output + next-step staging =====
        if (warp < 6) {
            float C[4];
#pragma unroll
            for (int e = 0; e < 4; e++) C[e] = 0.0f;
#pragma unroll 1
            for (int ks = 0; ks < KS4; ks++) {
                u32 Ah[4], Al[4];
                ldm_x4(Ah, aHiB + (u32)(C_O3 * 2 + ks * 32));
                ldm_x4(Al, aLoB + (u32)(C_O3 * 2 + ks * 32));
                uint4 b = __ldg(&g_B4[(warp * KS4 + ks) * 32 + lane]);
                mma_bf16(C, Ah, b.x, b.y);
                mma_bf16(C, Ah, b.z, b.w);
                mma_bf16(C, Al, b.x, b.y);
            }
            int col = warp * 8 + ccol;
            float bb0 = __ldg(&fc2b[col]), bb1 = __ldg(&fc2b[col + 1]);
            float v00 = tanhf(C[0] + bb0), v01 = tanhf(C[1] + bb1);
            float v10 = tanhf(C[2] + bb0), v11 = tanhf(C[3] + bb1);
            if (t >= 9) {
                *(float2*)&out[((size_t)(t - 9) * BB + row0 + crow) * FF + col]     = make_float2(v00, v01);
                *(float2*)&out[((size_t)(t - 9) * BB + row0 + crow + 8) * FF + col] = make_float2(v10, v11);
            }
            // stage inp for step t+1 (both arena slots)
            float n00 = v00, n01 = v01, n10 = v10, n11 = v11;
            if (t + 1 <= 9) {
                const float* tp0 = &tactiles[((size_t)(t + 1) * BB + row0 + crow) * FF + col];
                const float* tp1 = &tactiles[((size_t)(t + 1) * BB + row0 + crow + 8) * FF + col];
                n00 = tp0[0]; n01 = tp0[1]; n10 = tp1[0]; n11 = tp1[1];
            }
            splitStore(n00, aHi, aLo, crow * ASTR + C_INP + col);
            splitStore(n01, aHi, aLo, crow * ASTR + C_INP + col + 1);
            splitStore(n10, aHi, aLo, (crow + 8) * ASTR + C_INP + col);
            splitStore(n11, aHi, aLo, (crow + 8) * ASTR + C_INP + col + 1);
            splitStore(n00, aHi, aLo, crow * ASTR + C_INP2 + col);
            splitStore(n01, aHi, aLo, crow * ASTR + C_INP2 + col + 1);
            splitStore(n10, aHi, aLo, (crow + 8) * ASTR + C_INP2 + col);
            splitStore(n11, aHi, aLo, (crow + 8) * ASTR + C_INP2 + col + 1);
        } else {
            // stage til action part for step t+1
            int i2 = tid - 192;
            if (i2 >= 0 && i2 < 96 && t + 1 < NSTEP) {
                int r = i2 / 6, c = i2 % 6;
                float v = actions[((size_t)(t + 2) * BB + row0 + r) * AA + c];
                splitStore(v, aHi, aLo, r * ASTR + C_TIL + c);
            }
        }
        __syncthreads();
    }
}

// ---------------- launch ----------------
extern "C" void kernel_launch(void* const* d_in, const int* in_sizes, int n_in,
                              void* d_out, int out_size)
{
    (void)in_sizes; (void)n_in; (void)out_size;
    const float* tactiles = (const float*)d_in[0];
    const float* actions  = (const float*)d_in[1];
    const float* W_ih1    = (const float*)d_in[2];
    const float* W_hh1    = (const float*)d_in[3];
    const float* b_ih1    = (const float*)d_in[4];
    const float* b_hh1    = (const float*)d_in[5];
    const float* W_ih2    = (const float*)d_in[6];
    const float* W_hh2    = (const float*)d_in[7];
    const float* b_ih2    = (const float*)d_in[8];
    const float* b_hh2    = (const float*)d_in[9];
    const float* fc1_w    = (const float*)d_in[10];
    const float* fc1_b    = (const float*)d_in[11];
    const float* fc2_w    = (const float*)d_in[12];
    const float* fc2_b    = (const float*)d_in[13];
    float* out = (float*)d_out;

    prep_kernel<<<1024, 256>>>(W_ih1, W_hh1, b_ih1, b_hh1,
                               W_ih2, W_hh2, b_ih2, b_hh2,
                               fc1_w, fc2_w);

    size_t smem_bytes = (size_t)(2 * RRW * ASTR * 2) + (size_t)RRW * GSTR * 4;
    cudaFuncSetAttribute(actp_main, cudaFuncAttributeMaxDynamicSharedMemorySize, (int)smem_bytes);

    actp_main<<<NCTA, NTHREADS, smem_bytes>>>(tactiles, actions, fc1_b, fc2_b, out);
}

// round 16
// speedup vs baseline: 4.0427x; 1.0596x over previous
#include <cuda_runtime.h>
#include <cuda_bf16.h>
#include <cstring>

#define BB 4096
#define FF 48
#define AA 6
#define HH 200
#define NG 800
#define RRW 32              // rows per CTA
#define NSTEP 119
#define NTHREADS 640
#define NCTA (BB / RRW)     // 128

#define ASTR 744            // arena row stride (bf16 elems)
#define GSTR 808            // gates row stride (fp32)

// arena column bases
#define C_INP  0
#define C_H1   56
#define C_TIL  256
#define C_H2   272
#define C_INP2 472
#define C_O3   528

// GEMM shapes
#define KS1 16   // gemm1: A cols 0..255
#define KS2 26   // gemm2: A cols 56..471
#define KS3 16   // fc1:   A cols 272..527
#define KS4 13   // fc2:   A cols 528..735
#define NT1 100
#define NT3 25
#define NT4 6

typedef unsigned int u32;

// ---------------- packed weight fragments: uint4 = {bh0,bh1,bl0,bl1} ----------------
__device__ uint4 g_B1[NT1 * KS1 * 32];
__device__ uint4 g_B2[NT1 * KS2 * 32];
__device__ uint4 g_B3[NT3 * KS3 * 32];
__device__ uint4 g_B4[NT4 * KS4 * 32];
__device__ float g_b1[NG];
__device__ float g_b2[NG];

// ---------------- prep ----------------
__device__ __forceinline__ unsigned short bfbits(float v) {
    __nv_bfloat16 b = __float2bfloat16(v);
    unsigned short u; memcpy(&u, &b, 2); return u;
}
__device__ __forceinline__ uint4 packFrag(const float w[4]) {
    unsigned short h[4], l[4];
#pragma unroll
    for (int e = 0; e < 4; e++) {
        __nv_bfloat16 hb = __float2bfloat16(w[e]);
        h[e] = bfbits(w[e]);
        l[e] = bfbits(w[e] - __bfloat162float(hb));
    }
    uint4 r;
    r.x = (u32)h[0] | ((u32)h[1] << 16);
    r.y = (u32)h[2] | ((u32)h[3] << 16);
    r.z = (u32)l[0] | ((u32)l[1] << 16);
    r.w = (u32)l[2] | ((u32)l[3] << 16);
    return r;
}

__global__ void prep_kernel(const float* __restrict__ Wih1, const float* __restrict__ Whh1,
                            const float* __restrict__ bih1, const float* __restrict__ bhh1,
                            const float* __restrict__ Wih2, const float* __restrict__ Whh2,
                            const float* __restrict__ bih2, const float* __restrict__ bhh2,
                            const float* __restrict__ fc1w, const float* __restrict__ fc2w)
{
    int tid = blockIdx.x * blockDim.x + threadIdx.x;
    int stride = gridDim.x * blockDim.x;
    for (int i = tid; i < NG; i += stride) {
        g_b1[i] = bih1[i] + bhh1[i];
        g_b2[i] = bih2[i] + bhh2[i];
    }
    // GEMM1: K-span [inp48 | zp8 | h1 200] = 256
    for (int i = tid; i < NT1 * KS1 * 32; i += stride) {
        int lane = i & 31, ks = (i >> 5) % KS1, nt = i / (32 * KS1);
        int n = nt * 8 + (lane >> 2);
        int k0 = ks * 16 + (lane & 3) * 2;
        float w[4];
#pragma unroll
        for (int e = 0; e < 4; e++) {
            int k = k0 + (e >> 1) * 8 + (e & 1);
            float v;
            if (k < 48)       v = Wih1[n * 48 + k];
            else if (k < 56)  v = 0.0f;
            else              v = Whh1[n * 200 + (k - 56)];
            w[e] = v;
        }
        g_B1[i] = packFrag(w);
    }
    // GEMM2: K-span [h1 200 | til_folded 12 | zp4 | h2 200] = 416
    for (int i = tid; i < NT1 * KS2 * 32; i += stride) {
        int lane = i & 31, ks = (i >> 5) % KS2, nt = i / (32 * KS2);
        int n = nt * 8 + (lane >> 2);
        int k0 = ks * 16 + (lane & 3) * 2;
        float w[4];
#pragma unroll
        for (int e = 0; e < 4; e++) {
            int k = k0 + (e >> 1) * 8 + (e & 1);
            float v;
            if (k < 200) v = Wih2[n * 248 + k];
            else if (k < 212) {
                v = 0.0f;
#pragma unroll
                for (int r = 0; r < 4; r++) v += Wih2[n * 248 + 200 + (k - 200) + 12 * r];
            }
            else if (k < 216) v = 0.0f;
            else              v = Whh2[n * 200 + (k - 216)];
            w[e] = v;
        }
        g_B2[i] = packFrag(w);
    }
    // fc1: K-span [h2 200 | inp 48 | zp8] = 256, N = 200
    for (int i = tid; i < NT3 * KS3 * 32; i += stride) {
        int lane = i & 31, ks = (i >> 5) % KS3, nt = i / (32 * KS3);
        int n = nt * 8 + (lane >> 2);
        int k0 = ks * 16 + (lane & 3) * 2;
        float w[4];
#pragma unroll
        for (int e = 0; e < 4; e++) {
            int k = k0 + (e >> 1) * 8 + (e & 1);
            w[e] = (k < 248) ? fc1w[n * 248 + k] : 0.0f;
        }
        g_B3[i] = packFrag(w);
    }
    // fc2: K-span [o3 200 | zp8] = 208, N = 48
    for (int i = tid; i < NT4 * KS4 * 32; i += stride) {
        int lane = i & 31, ks = (i >> 5) % KS4, nt = i / (32 * KS4);
        int n = nt * 8 + (lane >> 2);
        int k0 = ks * 16 + (lane & 3) * 2;
        float w[4];
#pragma unroll
        for (int e = 0; e < 4; e++) {
            int k = k0 + (e >> 1) * 8 + (e & 1);
            w[e] = (k < 200) ? fc2w[n * 200 + k] : 0.0f;
        }
        g_B4[i] = packFrag(w);
    }
}

// ---------------- mma primitives ----------------
__device__ __forceinline__ u32 smem_u32(const void* p) {
    return (u32)__cvta_generic_to_shared(p);
}
__device__ __forceinline__ void ldm_x4(u32 a[4], u32 addr) {
    asm volatile("ldmatrix.sync.aligned.m8n8.x4.shared.b16 {%0,%1,%2,%3}, [%4];"
                 : "=r"(a[0]), "=r"(a[1]), "=r"(a[2]), "=r"(a[3]) : "r"(addr));
}
__device__ __forceinline__ void mma_bf16(float c[4], const u32 a[4], u32 b0, u32 b1) {
    asm volatile("mma.sync.aligned.m16n8k16.row.col.f32.bf16.bf16.f32 "
                 "{%0,%1,%2,%3}, {%4,%5,%6,%7}, {%8,%9}, {%0,%1,%2,%3};"
                 : "+f"(c[0]), "+f"(c[1]), "+f"(c[2]), "+f"(c[3])
                 : "r"(a[0]), "r"(a[1]), "r"(a[2]), "r"(a[3]), "r"(b0), "r"(b1));
}
__device__ __forceinline__ float sigm(float x) { return 1.0f / (1.0f + expf(-x)); }

__device__ __forceinline__ void splitStore(float v, __nv_bfloat16* hiA, __nv_bfloat16* loA, int idx) {
    __nv_bfloat16 h = __float2bfloat16(v);
    hiA[idx] = h;
    loA[idx] = __float2bfloat16(v - __bfloat162float(h));
}

// ---------------- main persistent kernel ----------------
__global__ void __launch_bounds__(NTHREADS, 1)
actp_main(const float* __restrict__ tactiles, const float* __restrict__ actions,
          const float* __restrict__ fc1b, const float* __restrict__ fc2b,
          float* __restrict__ out)
{
    extern __shared__ char smemraw[];
    __nv_bfloat16* aHi = (__nv_bfloat16*)smemraw;
    __nv_bfloat16* aLo = aHi + RRW * ASTR;
    float* gates = (float*)(smemraw + 2 * RRW * ASTR * 2);

    const int tid  = threadIdx.x;
    const int lane = tid & 31;
    const int warp = tid >> 5;
    const int row0 = blockIdx.x * RRW;

    // zero arena
    {
        u32* z = (u32*)smemraw;
        int nz = (2 * RRW * ASTR * 2) / 4;
        for (int i = tid; i < nz; i += NTHREADS) z[i] = 0;
    }
    __syncthreads();

    // prologue staging
    for (int idx = tid; idx < RRW * FF; idx += NTHREADS) {
        int r = idx / FF, c = idx % FF;
        float v = tactiles[((size_t)0 * BB + row0 + r) * FF + c];
        splitStore(v, aHi, aLo, r * ASTR + C_INP + c);
        splitStore(v, aHi, aLo, r * ASTR + C_INP2 + c);
    }
    for (int idx = tid; idx < RRW * 12; idx += NTHREADS) {
        int r = idx / 12, c = idx % 12;
        float v = (c < 6)
            ? actions[((size_t)1 * BB + row0 + r) * AA + c]
            : actions[(size_t)(row0 + r) * AA + (c - 6)];
        splitStore(v, aHi, aLo, r * ASTR + C_TIL + c);
    }
    float c1s[10], c2s[10];
#pragma unroll
    for (int i = 0; i < 10; i++) { c1s[i] = 0.0f; c2s[i] = 0.0f; }
    __syncthreads();

    // ldmatrix lane geometry (two mtiles: rows +0 and +16)
    const int mq   = lane >> 3;
    const int ldr  = (mq & 1) * 8 + (lane & 7);
    const int ldc  = (mq >> 1) * 8;
    const u32 aHiB0 = smem_u32(aHi) + (u32)(ldr * ASTR + ldc) * 2;
    const u32 aLoB0 = smem_u32(aLo) + (u32)(ldr * ASTR + ldc) * 2;
    const u32 aHiB1 = aHiB0 + (u32)(16 * ASTR) * 2;
    const u32 aLoB1 = aLoB0 + (u32)(16 * ASTR) * 2;
    const int crow = lane >> 2;           // C fragment row
    const int ccol = (lane & 3) * 2;      // C fragment col base

    for (int t = 0; t < NSTEP; t++) {
        // ===== Phase A: GEMM1 -> gates =====
        {
            float C[5][2][4];
#pragma unroll
            for (int j = 0; j < 5; j++)
#pragma unroll
                for (int m = 0; m < 2; m++)
#pragma unroll
                    for (int e = 0; e < 4; e++) C[j][m][e] = 0.0f;
            const int ntb = warp * 5;
#pragma unroll 1
            for (int ks = 0; ks < KS1; ks++) {
                u32 Ah0[4], Al0[4], Ah1[4], Al1[4];
                ldm_x4(Ah0, aHiB0 + (u32)(C_INP * 2 + ks * 32));
                ldm_x4(Al0, aLoB0 + (u32)(C_INP * 2 + ks * 32));
                ldm_x4(Ah1, aHiB1 + (u32)(C_INP * 2 + ks * 32));
                ldm_x4(Al1, aLoB1 + (u32)(C_INP * 2 + ks * 32));
#pragma unroll
                for (int j = 0; j < 5; j++) {
                    uint4 b = __ldg(&g_B1[((ntb + j) * KS1 + ks) * 32 + lane]);
                    mma_bf16(C[j][0], Ah0, b.x, b.y);
                    mma_bf16(C[j][0], Ah0, b.z, b.w);
                    mma_bf16(C[j][0], Al0, b.x, b.y);
                    mma_bf16(C[j][1], Ah1, b.x, b.y);
                    mma_bf16(C[j][1], Ah1, b.z, b.w);
                    mma_bf16(C[j][1], Al1, b.x, b.y);
                }
            }
#pragma unroll
            for (int j = 0; j < 5; j++) {
#pragma unroll
                for (int m = 0; m < 2; m++) {
                    int col = (ntb + j) * 8 + ccol;
                    int rb = crow + 16 * m;
                    *(float2*)&gates[rb * GSTR + col]       = make_float2(C[j][m][0], C[j][m][1]);
                    *(float2*)&gates[(rb + 8) * GSTR + col] = make_float2(C[j][m][2], C[j][m][3]);
                }
            }
        }
        __syncthreads();

        // ===== Phase B: LSTM1 cell update -> h1 =====
#pragma unroll
        for (int i = 0; i < 10; i++) {
            int idx = tid + NTHREADS * i;
            int r = idx / HH, u = idx % HH;
            float gi = gates[r * GSTR + u]        + __ldg(&g_b1[u]);
            float gf = gates[r * GSTR + u + 200]  + __ldg(&g_b1[u + 200]);
            float gg = gates[r * GSTR + u + 400]  + __ldg(&g_b1[u + 400]);
            float go = gates[r * GSTR + u + 600]  + __ldg(&g_b1[u + 600]);
            float c = sigm(gf) * c1s[i] + sigm(gi) * tanhf(gg);
            c1s[i] = c;
            splitStore(sigm(go) * tanhf(c), aHi, aLo, r * ASTR + C_H1 + u);
        }
        __syncthreads();

        // ===== Phase C: GEMM2 -> gates =====
        {
            float C[5][2][4];
#pragma unroll
            for (int j = 0; j < 5; j++)
#pragma unroll
                for (int m = 0; m < 2; m++)
#pragma unroll
                    for (int e = 0; e < 4; e++) C[j][m][e] = 0.0f;
            const int ntb = warp * 5;
#pragma unroll 1
            for (int ks = 0; ks < KS2; ks++) {
                u32 Ah0[4], Al0[4], Ah1[4], Al1[4];
                ldm_x4(Ah0, aHiB0 + (u32)(C_H1 * 2 + ks * 32));
                ldm_x4(Al0, aLoB0 + (u32)(C_H1 * 2 + ks * 32));
                ldm_x4(Ah1, aHiB1 + (u32)(C_H1 * 2 + ks * 32));
                ldm_x4(Al1, aLoB1 + (u32)(C_H1 * 2 + ks * 32));
#pragma unroll
                for (int j = 0; j < 5; j++) {
                    uint4 b = __ldg(&g_B2[((ntb + j) * KS2 + ks) * 32 + lane]);
                    mma_bf16(C[j][0], Ah0, b.x, b.y);
                    mma_bf16(C[j][0], Ah0, b.z, b.w);
                    mma_bf16(C[j][0], Al0, b.x, b.y);
                    mma_bf16(C[j][1], Ah1, b.x, b.y);
                    mma_bf16(C[j][1], Ah1, b.z, b.w);
                    mma_bf16(C[j][1], Al1, b.x, b.y);
                }
            }
#pragma unroll
            for (int j = 0; j < 5; j++) {
#pragma unroll
                for (int m = 0; m < 2; m++) {
                    int col = (ntb + j) * 8 + ccol;
                    int rb = crow + 16 * m;
                    *(float2*)&gates[rb * GSTR + col]       = make_float2(C[j][m][0], C[j][m][1]);
                    *(float2*)&gates[(rb + 8) * GSTR + col] = make_float2(C[j][m][2], C[j][m][3]);
                }
            }
        }
        __syncthreads();

        // ===== Phase D: LSTM2 cell update -> h2 =====
#pragma unroll
        for (int i = 0; i < 10; i++) {
            int idx = tid + NTHREADS * i;
            int r = idx / HH, u = idx % HH;
            float gi = gates[r * GSTR + u]        + __ldg(&g_b2[u]);
            float gf = gates[r * GSTR + u + 200]  + __ldg(&g_b2[u + 200]);
            float gg = gates[r * GSTR + u + 400]  + __ldg(&g_b2[u + 400]);
            float go = gates[r * GSTR + u + 600]  + __ldg(&g_b2[u + 600]);
            float c = sigm(gf) * c2s[i] + sigm(gi) * tanhf(gg);
            c2s[i] = c;
            splitStore(sigm(go) * tanhf(c), aHi, aLo, r * ASTR + C_H2 + u);
        }
        __syncthreads();

        // ===== Phase E: fc1 GEMM -> gates[0..199] (preacts), 50 warp-tiles =====
        {
            float C[3][4];
#pragma unroll
            for (int j = 0; j < 3; j++)
#pragma unroll
                for (int e = 0; e < 4; e++) C[j][e] = 0.0f;
            const int cnt = (warp < 10) ? 3 : 2;
#pragma unroll 1
            for (int ks = 0; ks < KS3; ks++) {
                u32 Ah0[4], Al0[4], Ah1[4], Al1[4];
                ldm_x4(Ah0, aHiB0 + (u32)(C_H2 * 2 + ks * 32));
                ldm_x4(Al0, aLoB0 + (u32)(C_H2 * 2 + ks * 32));
                ldm_x4(Ah1, aHiB1 + (u32)(C_H2 * 2 + ks * 32));
                ldm_x4(Al1, aLoB1 + (u32)(C_H2 * 2 + ks * 32));
#pragma unroll
                for (int j = 0; j < 3; j++) {
                    if (j < cnt) {
                        int tI = warp + 20 * j;      // 0..49
                        int nt = tI % NT3, mt = tI / NT3;
                        uint4 b = __ldg(&g_B3[(nt * KS3 + ks) * 32 + lane]);
                        const u32* Ah = mt ? Ah1 : Ah0;
                        const u32* Al = mt ? Al1 : Al0;
                        mma_bf16(C[j], Ah, b.x, b.y);
                        mma_bf16(C[j], Ah, b.z, b.w);
                        mma_bf16(C[j], Al, b.x, b.y);
                    }
                }
            }
#pragma unroll
            for (int j = 0; j < 3; j++) {
                if (j < cnt) {
                    int tI = warp + 20 * j;
                    int nt = tI % NT3, mt = tI / NT3;
                    int col = nt * 8 + ccol;
                    int rb = crow + 16 * mt;
                    *(float2*)&gates[rb * GSTR + col]       = make_float2(C[j][0], C[j][1]);
                    *(float2*)&gates[(rb + 8) * GSTR + col] = make_float2(C[j][2], C[j][3]);
                }
            }
        }
        __syncthreads();

        // ===== Phase F: o3 = tanh(preact + fc1b) -> arena =====
#pragma unroll
        for (int i = 0; i < 10; i++) {
            int idx = tid + NTHREADS * i;
            int r = idx / HH, u = idx % HH;
            float v = tanhf(gates[r * GSTR + u] + __ldg(&fc1b[u]));
            splitStore(v, aHi, aLo, r * ASTR + C_O3 + u);
        }
        __syncthreads();

        // ===== Phase G: fc2 GEMM + output + next-step staging =====
        if (warp < 12) {
            int nt = warp % NT4, mt = warp / NT4;
            float C[4];
#pragma unroll
            for (int e = 0; e < 4; e++) C[e] = 0.0f;
            const u32 aH = mt ? aHiB1 : aHiB0;
            const u32 aL = mt ? aLoB1 : aLoB0;
#pragma unroll 1
            for (int ks = 0; ks < KS4; ks++) {
                u32 Ah[4], Al[4];
                ldm_x4(Ah, aH + (u32)(C_O3 * 2 + ks * 32));
                ldm_x4(Al, aL + (u32)(C_O3 * 2 + ks * 32));
                uint4 b = __ldg(&g_B4[(nt * KS4 + ks) * 32 + lane]);
                mma_bf16(C, Ah, b.x, b.y);
                mma_bf16(C, Ah, b.z, b.w);
                mma_bf16(C, Al, b.x, b.y);
            }
            int col = nt * 8 + ccol;
            int r0 = crow + 16 * mt, r1 = crow + 8 + 16 * mt;
            float bb0 = __ldg(&fc2b[col]), bb1 = __ldg(&fc2b[col + 1]);
            float v00 = tanhf(C[0] + bb0), v01 = tanhf(C[1] + bb1);
            float v10 = tanhf(C[2] + bb0), v11 = tanhf(C[3] + bb1);
            if (t >= 9) {
                *(float2*)&out[((size_t)(t - 9) * BB + row0 + r0) * FF + col] = make_float2(v00, v01);
                *(float2*)&out[((size_t)(t - 9) * BB + row0 + r1) * FF + col] = make_float2(v10, v11);
            }
            float n00 = v00, n01 = v01, n10 = v10, n11 = v11;
            if (t + 1 <= 9) {
                const float* tp0 = &tactiles[((size_t)(t + 1) * BB + row0 + r0) * FF + col];
                const float* tp1 = &tactiles[((size_t)(t + 1) * BB + row0 + r1) * FF + col];
                n00 = tp0[0]; n01 = tp0[1]; n10 = tp1[0]; n11 = tp1[1];
            }
            splitStore(n00, aHi, aLo, r0 * ASTR + C_INP + col);
            splitStore(n01, aHi, aLo, r0 * ASTR + C_INP + col + 1);
            splitStore(n10, aHi, aLo, r1 * ASTR + C_INP + col);
            splitStore(n11, aHi, aLo, r1 * ASTR + C_INP + col + 1);
            splitStore(n00, aHi, aLo, r0 * ASTR + C_INP2 + col);
            splitStore(n01, aHi, aLo, r0 * ASTR + C_INP2 + col + 1);
            splitStore(n10, aHi, aLo, r1 * ASTR + C_INP2 + col);
            splitStore(n11, aHi, aLo, r1 * ASTR + C_INP2 + col + 1);
        } else {
            // stage til action part for step t+1
            int i2 = tid - 384;
            if (i2 >= 0 && i2 < RRW * 6 && t + 1 < NSTEP) {
                int r = i2 / 6, c = i2 % 6;
                float v = actions[((size_t)(t + 2) * BB + row0 + r) * AA + c];
                splitStore(v, aHi, aLo, r * ASTR + C_TIL + c);
            }
        }
        __syncthreads();
    }
}

// ---------------- launch ----------------
extern "C" void kernel_launch(void* const* d_in, const int* in_sizes, int n_in,
                              void* d_out, int out_size)
{
    (void)in_sizes; (void)n_in; (void)out_size;
    const float* tactiles = (const float*)d_in[0];
    const float* actions  = (const float*)d_in[1];
    const float* W_ih1    = (const float*)d_in[2];
    const float* W_hh1    = (const float*)d_in[3];
    const float* b_ih1    = (const float*)d_in[4];
    const float* b_hh1    = (const float*)d_in[5];
    const float* W_ih2    = (const float*)d_in[6];
    const float* W_hh2    = (const float*)d_in[7];
    const float* b_ih2    = (const float*)d_in[8];
    const float* b_hh2    = (const float*)d_in[9];
    const float* fc1_w    = (const float*)d_in[10];
    const float* fc1_b    = (const float*)d_in[11];
    const float* fc2_w    = (const float*)d_in[12];
    const float* fc2_b    = (const float*)d_in[13];
    float* out = (float*)d_out;

    prep_kernel<<<1024, 256>>>(W_ih1, W_hh1, b_ih1, b_hh1,
                               W_ih2, W_hh2, b_ih2, b_hh2,
                               fc1_w, fc2_w);

    size_t smem_bytes = (size_t)(2 * RRW * ASTR * 2) + (size_t)RRW * GSTR * 4;
    cudaFuncSetAttribute(actp_main, cudaFuncAttributeMaxDynamicSharedMemorySize, (int)smem_bytes);

    actp_main<<<NCTA, NTHREADS, smem_bytes>>>(tactiles, actions, fc1_b, fc2_b, out);
}